// round 13
// baseline (speedup 1.0000x reference)
#include <cuda_runtime.h>
#include <cuda_fp16.h>
#include <cstdint>
#include <math.h>

// Problem constants
#define BSZ   4
#define N1    4096
#define N2    256
#define DIM   1024
#define HEADS 16
#define DH    64
#define INNER 1024
#define EPS   1e-5f

// ---------------------------------------------------------------------------
// Scratch (device globals). fp16 (hi, lo) pairs where the softmax path needs
// near-fp32 precision; single fp16 on the unamplified V/P/ao path.
// ---------------------------------------------------------------------------
__device__ __half g_xnh[BSZ * N1 * DIM];
__device__ __half g_xnl[BSZ * N1 * DIM];
__device__ __half g_lnh[BSZ * N2 * DIM];
__device__ __half g_lnl[BSZ * N2 * DIM];
__device__ __half g_wqTh[INNER * DIM];
__device__ __half g_wqTl[INNER * DIM];
__device__ __half g_wkvTh[2 * INNER * DIM];
__device__ __half g_wkvTl[2 * INNER * DIM];
__device__ __half g_woTh[DIM * INNER];
__device__ __half g_woTl[DIM * INNER];
__device__ __half g_kh[BSZ * N1 * INNER];
__device__ __half g_kl[BSZ * N1 * INNER];
__device__ __half g_v [BSZ * N1 * INNER];
__device__ __half g_ao[BSZ * N2 * INNER];
__device__ float  g_q [BSZ * N2 * INNER];

// ---------------------------------------------------------------------------
// Helpers
// ---------------------------------------------------------------------------
__device__ __forceinline__ void mma_f16(float* c, const uint32_t* a, const uint32_t* b) {
    asm volatile(
        "mma.sync.aligned.m16n8k16.row.col.f32.f16.f16.f32 "
        "{%0,%1,%2,%3}, {%4,%5,%6,%7}, {%8,%9}, {%0,%1,%2,%3};"
        : "+f"(c[0]), "+f"(c[1]), "+f"(c[2]), "+f"(c[3])
        : "r"(a[0]), "r"(a[1]), "r"(a[2]), "r"(a[3]), "r"(b[0]), "r"(b[1]));
}

__device__ __forceinline__ void ldsm4(uint32_t* r, uint32_t addr) {
    asm volatile("ldmatrix.sync.aligned.m8n8.x4.shared.b16 {%0,%1,%2,%3}, [%4];"
                 : "=r"(r[0]), "=r"(r[1]), "=r"(r[2]), "=r"(r[3]) : "r"(addr));
}

__device__ __forceinline__ void ldsm2(uint32_t* r, uint32_t addr) {
    asm volatile("ldmatrix.sync.aligned.m8n8.x2.shared.b16 {%0,%1}, [%2];"
                 : "=r"(r[0]), "=r"(r[1]) : "r"(addr));
}

__device__ __forceinline__ uint32_t pack_f16(float x, float y) {
    __half2 h = __floats2half2_rn(x, y);
    return *reinterpret_cast<uint32_t*>(&h);
}

__device__ __forceinline__ uint32_t smem_u32p(const void* p) {
    uint32_t a;
    asm("{ .reg .u64 t; cvta.to.shared.u64 t, %1; cvt.u32.u64 %0, t; }" : "=r"(a) : "l"(p));
    return a;
}

__device__ __forceinline__ void cp16(uint32_t dst, const void* src) {
    asm volatile("cp.async.cg.shared.global [%0], [%1], 16;" :: "r"(dst), "l"(src));
}

__device__ __forceinline__ float block_sum_256(float v, float* sbuf) {
    #pragma unroll
    for (int off = 16; off > 0; off >>= 1)
        v += __shfl_xor_sync(0xffffffffu, v, off);
    int w = threadIdx.x >> 5;
    if ((threadIdx.x & 31) == 0) sbuf[w] = v;
    __syncthreads();
    float r = (threadIdx.x < 8) ? sbuf[threadIdx.x] : 0.0f;
    #pragma unroll
    for (int off = 4; off > 0; off >>= 1)
        r += __shfl_xor_sync(0xffffffffu, r, off);
    if (threadIdx.x == 0) sbuf[0] = r;
    __syncthreads();
    float out = sbuf[0];
    __syncthreads();
    return out;
}

// ---------------------------------------------------------------------------
// LayerNorm (row of 1024) -> split fp16 hi/lo outputs.
// ---------------------------------------------------------------------------
__global__ void ln_split_kernel(const float* __restrict__ x,
                                const float* __restrict__ w,
                                const float* __restrict__ b,
                                __half* __restrict__ yh,
                                __half* __restrict__ yl) {
    __shared__ float sbuf[8];
    size_t row = blockIdx.x;
    int t = threadIdx.x;

    const float4 v = ((const float4*)(x + row * DIM))[t];
    float s = v.x + v.y + v.z + v.w;
    float tot = block_sum_256(s, sbuf);
    float mean = tot * (1.0f / DIM);

    float dx = v.x - mean, dy = v.y - mean, dz = v.z - mean, dw = v.w - mean;
    float sq = dx * dx + dy * dy + dz * dz + dw * dw;
    float vtot = block_sum_256(sq, sbuf);
    float inv = rsqrtf(vtot * (1.0f / DIM) + EPS);

    const float4 wv = ((const float4*)w)[t];
    const float4 bv = ((const float4*)b)[t];
    float o0 = dx * inv * wv.x + bv.x;
    float o1 = dy * inv * wv.y + bv.y;
    float o2 = dz * inv * wv.z + bv.z;
    float o3 = dw * inv * wv.w + bv.w;

    float h0 = __half2float(__float2half_rn(o0));
    float h1 = __half2float(__float2half_rn(o1));
    float h2 = __half2float(__float2half_rn(o2));
    float h3 = __half2float(__float2half_rn(o3));

    ((uint2*)(yh + row * DIM))[t] = make_uint2(pack_f16(h0, h1), pack_f16(h2, h3));
    ((uint2*)(yl + row * DIM))[t] = make_uint2(pack_f16(o0 - h0, o1 - h1),
                                               pack_f16(o2 - h2, o3 - h3));
}

// ---------------------------------------------------------------------------
// 32x32 tiled transpose with fp16 hi/lo split
// ---------------------------------------------------------------------------
__global__ void transpose_split_kernel(const float* __restrict__ in,
                                       __half* __restrict__ outh,
                                       __half* __restrict__ outl,
                                       int R, int C) {
    __shared__ float t[32][33];
    int c0 = blockIdx.x * 32, r0 = blockIdx.y * 32;
    #pragma unroll
    for (int i = 0; i < 32; i += 8)
        t[threadIdx.y + i][threadIdx.x] =
            in[(size_t)(r0 + threadIdx.y + i) * C + c0 + threadIdx.x];
    __syncthreads();
    #pragma unroll
    for (int i = 0; i < 32; i += 8) {
        float v = t[threadIdx.x][threadIdx.y + i];
        __half h = __float2half_rn(v);
        size_t idx = (size_t)(c0 + threadIdx.y + i) * R + r0 + threadIdx.x;
        outh[idx] = h;
        outl[idx] = __float2half_rn(v - __half2float(h));
    }
}

// ---------------------------------------------------------------------------
// 3-term fp16 GEMM (both operands split pairs), ldmatrix + 3-stage cp.async:
//   C = Ah·Bh^T + Ah·Bl^T + Al·Bh^T
// BK=32, 256 thr (8 warps, 2x4, 64x32/warp), ONE barrier per stage.
// ---------------------------------------------------------------------------
#define RS 20
#define MATW (128 * RS)
#define ST3_W (4 * MATW)
#define G3_SMEM (3 * ST3_W * 4)         // 122880 B

__global__ void __launch_bounds__(256, 1)
gemm3_kernel(const __half* __restrict__ Ah, const __half* __restrict__ Al,
             const __half* __restrict__ Bh, const __half* __restrict__ Bl,
             float* __restrict__ C, __half* __restrict__ Ch, __half* __restrict__ Cl,
             int M, int N, int K, int split_out) {
    extern __shared__ uint32_t sh[];
    const uint32_t sbase = smem_u32p(sh);

    const int tid  = threadIdx.x;
    const int lane = tid & 31;
    const int wid  = tid >> 5;
    const int warp_m = wid >> 2;
    const int warp_n = wid & 3;
    const int bm = blockIdx.y * 128;
    const int bn = blockIdx.x * 128;

    // loader mapping
    const int matB = tid >> 7;
    const int lt   = tid & 127;
    const int lf   = lt & 3;
    const int lr0  = lt >> 2;
    const __half* srcH = matB ? (Bh + (size_t)bn * K) : (Ah + (size_t)bm * K);
    const __half* srcL = matB ? (Bl + (size_t)bn * K) : (Al + (size_t)bm * K);
    const uint32_t dH_bytes = (matB ? 2 * MATW : 0) * 4;
    const uint32_t dL_bytes = dH_bytes + MATW * 4;

    // ldmatrix address offsets (bytes, within stage)
    const uint32_t arow_off =
        ((uint32_t)(warp_m * 64 + (lane & 7) + ((lane >> 3) & 1) * 8) * RS
         + (uint32_t)(lane >> 4) * 4) * 4;
    const uint32_t brow_off =
        ((uint32_t)(warp_n * 32 + (lane & 7)) * RS
         + (uint32_t)((lane >> 3) & 1) * 4) * 4;

    float acc[4][4][4];
    #pragma unroll
    for (int i = 0; i < 4; i++)
        #pragma unroll
        for (int j = 0; j < 4; j++)
            #pragma unroll
            for (int k = 0; k < 4; k++) acc[i][j][k] = 0.0f;

    const int S = K >> 5;

    // prologue: stages 0, 1 into buffers 0, 1
    #pragma unroll
    for (int pre = 0; pre < 2; pre++) {
        uint32_t stbase = sbase + (uint32_t)(pre * ST3_W * 4);
        #pragma unroll
        for (int i = 0; i < 4; i++) {
            int row = lr0 + 32 * i;
            uint32_t doff = (uint32_t)((row * RS + lf * 4) * 4);
            cp16(stbase + dH_bytes + doff, srcH + (size_t)row * K + pre * 32 + lf * 8);
            cp16(stbase + dL_bytes + doff, srcL + (size_t)row * K + pre * 32 + lf * 8);
        }
        asm volatile("cp.async.commit_group;" ::: "memory");
    }

    int buf = 0;        // buffer for stage s
    int ibuf = 2;       // buffer for stage s+2
    for (int s = 0; s < S; s++) {
        asm volatile("cp.async.wait_group 1;" ::: "memory");   // stage s landed (this thread)
        __syncthreads();                                       // published + buffer (s+2)%3 free

        if (s + 2 < S) {
            int k0 = (s + 2) * 32;
            uint32_t stbase = sbase + (uint32_t)(ibuf * ST3_W * 4);
            #pragma unroll
            for (int i = 0; i < 4; i++) {
                int row = lr0 + 32 * i;
                uint32_t doff = (uint32_t)((row * RS + lf * 4) * 4);
                cp16(stbase + dH_bytes + doff, srcH + (size_t)row * K + k0 + lf * 8);
                cp16(stbase + dL_bytes + doff, srcL + (size_t)row * K + k0 + lf * 8);
            }
        }
        asm volatile("cp.async.commit_group;" ::: "memory");

        // ---- MMA phase on buffer `buf` ----
        const uint32_t stb = sbase + (uint32_t)(buf * ST3_W * 4);
        const uint32_t aAH = stb + arow_off;
        const uint32_t bBH = stb + 2 * MATW * 4 + brow_off;

        #pragma unroll
        for (int ks = 0; ks < 2; ks++) {
            uint32_t bh[4][2], bl[4][2];
            #pragma unroll
            for (int nb = 0; nb < 4; nb++) {
                uint32_t ba = bBH + nb * (8 * RS * 4) + ks * 32;
                ldsm2(bh[nb], ba);
                ldsm2(bl[nb], ba + MATW * 4);
            }
            #pragma unroll
            for (int ma = 0; ma < 4; ma++) {
                uint32_t aa = aAH + ma * (16 * RS * 4) + ks * 32;
                uint32_t ah[4], al[4];
                ldsm4(ah, aa);
                ldsm4(al, aa + MATW * 4);
                #pragma unroll
                for (int nb = 0; nb < 4; nb++) {
                    mma_f16(acc[ma][nb], ah, bh[nb]);
                    mma_f16(acc[ma][nb], ah, bl[nb]);
                    mma_f16(acc[ma][nb], al, bh[nb]);
                }
            }
        }

        buf = (buf == 2) ? 0 : buf + 1;
        ibuf = (ibuf == 2) ? 0 : ibuf + 1;
    }

    uint32_t* Hh = (uint32_t*)Ch;
    uint32_t* Hl = (uint32_t*)Cl;
    #pragma unroll
    for (int ma = 0; ma < 4; ma++) {
        int row = bm + warp_m * 64 + ma * 16 + (lane >> 2);
        #pragma unroll
        for (int nb = 0; nb < 4; nb++) {
            int col = bn + warp_n * 32 + nb * 8 + (lane & 3) * 2;
            if (split_out) {
                float v0 = acc[ma][nb][0], v1 = acc[ma][nb][1];
                float v2 = acc[ma][nb][2], v3 = acc[ma][nb][3];
                float h0 = __half2float(__float2half_rn(v0));
                float h1 = __half2float(__float2half_rn(v1));
                float h2 = __half2float(__float2half_rn(v2));
                float h3 = __half2float(__float2half_rn(v3));
                size_t i0 = ((size_t)row * N + col) >> 1;
                size_t i1 = ((size_t)(row + 8) * N + col) >> 1;
                Hh[i0] = pack_f16(h0, h1);
                Hl[i0] = pack_f16(v0 - h0, v1 - h1);
                Hh[i1] = pack_f16(h2, h3);
                Hl[i1] = pack_f16(v2 - h2, v3 - h3);
            } else {
                *(float2*)(C + (size_t)row * N + col) =
                    make_float2(acc[ma][nb][0], acc[ma][nb][1]);
                *(float2*)(C + (size_t)(row + 8) * N + col) =
                    make_float2(acc[ma][nb][2], acc[ma][nb][3]);
            }
        }
    }
}

// ---------------------------------------------------------------------------
// 2-term fp16 GEMM (A single, B split pair), ldmatrix + 3-stage cp.async:
//   C = A·Bh^T + A·Bl^T
// ---------------------------------------------------------------------------
#define ST2_W (3 * MATW)
#define G2_SMEM (3 * ST2_W * 4)         // 92160 B

__global__ void __launch_bounds__(256, 1)
gemm2_kernel(const __half* __restrict__ A,
             const __half* __restrict__ Bh, const __half* __restrict__ Bl,
             float* __restrict__ C, __half* __restrict__ Ch,
             int M, int N, int K, int half_out) {
    extern __shared__ uint32_t sh[];
    const uint32_t sbase = smem_u32p(sh);

    const int tid  = threadIdx.x;
    const int lane = tid & 31;
    const int wid  = tid >> 5;
    const int warp_m = wid >> 2;
    const int warp_n = wid & 3;
    const int bm = blockIdx.y * 128;
    const int bn = blockIdx.x * 128;

    const int matB = tid >> 7;
    const int lt   = tid & 127;
    const int lf   = lt & 3;
    const int lr0  = lt >> 2;
    const __half* srcA  = A  + (size_t)bm * K;
    const __half* srcBh = Bh + (size_t)bn * K;
    const __half* srcBl = Bl + (size_t)bn * K;

    const uint32_t arow_off =
        ((uint32_t)(warp_m * 64 + (lane & 7) + ((lane >> 3) & 1) * 8) * RS
         + (uint32_t)(lane >> 4) * 4) * 4;
    const uint32_t brow_off =
        ((uint32_t)(warp_n * 32 + (lane & 7)) * RS
         + (uint32_t)((lane >> 3) & 1) * 4) * 4;

    float acc[4][4][4];
    #pragma unroll
    for (int i = 0; i < 4; i++)
        #pragma unroll
        for (int j = 0; j < 4; j++)
            #pragma unroll
            for (int k = 0; k < 4; k++) acc[i][j][k] = 0.0f;

    const int S = K >> 5;

    #pragma unroll
    for (int pre = 0; pre < 2; pre++) {
        uint32_t stbase = sbase + (uint32_t)(pre * ST2_W * 4);
        #pragma unroll
        for (int i = 0; i < 4; i++) {
            int row = lr0 + 32 * i;
            uint32_t doff = (uint32_t)((row * RS + lf * 4) * 4);
            if (matB == 0) {
                cp16(stbase + doff, srcA + (size_t)row * K + pre * 32 + lf * 8);
            } else {
                cp16(stbase + MATW * 4 + doff,     srcBh + (size_t)row * K + pre * 32 + lf * 8);
                cp16(stbase + 2 * MATW * 4 + doff, srcBl + (size_t)row * K + pre * 32 + lf * 8);
            }
        }
        asm volatile("cp.async.commit_group;" ::: "memory");
    }

    int buf = 0, ibuf = 2;
    for (int s = 0; s < S; s++) {
        asm volatile("cp.async.wait_group 1;" ::: "memory");
        __syncthreads();

        if (s + 2 < S) {
            int k0 = (s + 2) * 32;
            uint32_t stbase = sbase + (uint32_t)(ibuf * ST2_W * 4);
            #pragma unroll
            for (int i = 0; i < 4; i++) {
                int row = lr0 + 32 * i;
                uint32_t doff = (uint32_t)((row * RS + lf * 4) * 4);
                if (matB == 0) {
                    cp16(stbase + doff, srcA + (size_t)row * K + k0 + lf * 8);
                } else {
                    cp16(stbase + MATW * 4 + doff,     srcBh + (size_t)row * K + k0 + lf * 8);
                    cp16(stbase + 2 * MATW * 4 + doff, srcBl + (size_t)row * K + k0 + lf * 8);
                }
            }
        }
        asm volatile("cp.async.commit_group;" ::: "memory");

        const uint32_t stb = sbase + (uint32_t)(buf * ST2_W * 4);
        const uint32_t aA  = stb + arow_off;
        const uint32_t bBH = stb + MATW * 4 + brow_off;

        #pragma unroll
        for (int ks = 0; ks < 2; ks++) {
            uint32_t bh[4][2], bl[4][2];
            #pragma unroll
            for (int nb = 0; nb < 4; nb++) {
                uint32_t ba = bBH + nb * (8 * RS * 4) + ks * 32;
                ldsm2(bh[nb], ba);
                ldsm2(bl[nb], ba + MATW * 4);
            }
            #pragma unroll
            for (int ma = 0; ma < 4; ma++) {
                uint32_t a[4];
                ldsm4(a, aA + ma * (16 * RS * 4) + ks * 32);
                #pragma unroll
                for (int nb = 0; nb < 4; nb++) {
                    mma_f16(acc[ma][nb], a, bh[nb]);
                    mma_f16(acc[ma][nb], a, bl[nb]);
                }
            }
        }

        buf = (buf == 2) ? 0 : buf + 1;
        ibuf = (ibuf == 2) ? 0 : ibuf + 1;
    }

    uint32_t* H = (uint32_t*)Ch;
    #pragma unroll
    for (int ma = 0; ma < 4; ma++) {
        int row = bm + warp_m * 64 + ma * 16 + (lane >> 2);
        #pragma unroll
        for (int nb = 0; nb < 4; nb++) {
            int col = bn + warp_n * 32 + nb * 8 + (lane & 3) * 2;
            if (half_out) {
                H[((size_t)row * N + col) >> 1] =
                    pack_f16(acc[ma][nb][0], acc[ma][nb][1]);
                H[((size_t)(row + 8) * N + col) >> 1] =
                    pack_f16(acc[ma][nb][2], acc[ma][nb][3]);
            } else {
                *(float2*)(C + (size_t)row * N + col) =
                    make_float2(acc[ma][nb][0], acc[ma][nb][1]);
                *(float2*)(C + (size_t)(row + 8) * N + col) =
                    make_float2(acc[ma][nb][2], acc[ma][nb][3]);
            }
        }
    }
}

// ---------------------------------------------------------------------------
// Tensor-core flash attention per (b, h, 64-query tile).  (unchanged R10)
// ---------------------------------------------------------------------------
#define AST 36
#define AMAT (64 * AST)
#define A_KH 0
#define A_KL (AMAT)
#define A_VH (2 * AMAT)
#define A_PH (3 * AMAT)
#define A_RED (4 * AMAT)
#define ATT_SMEM ((4 * AMAT + 256) * 4)

__global__ void __launch_bounds__(256, 2)
attn_tc_kernel(const float* __restrict__ q,
               const __half* __restrict__ kh,
               const __half* __restrict__ kl,
               const __half* __restrict__ vv,
               const float* __restrict__ shift,
               const float* __restrict__ scale,
               __half* __restrict__ outp) {
    extern __shared__ uint32_t ash[];
    float* redmax = (float*)(ash + A_RED);
    float* redsum = redmax + 128;

    const int bh = blockIdx.x;
    const int b  = bh >> 4;
    const int h  = bh & 15;
    const int qt = blockIdx.y;

    const int tid  = threadIdx.x;
    const int lane = tid & 31;
    const int wid  = tid >> 5;
    const int wm   = wid >> 1;
    const int wx   = wid & 1;
    const int r    = lane >> 2;
    const int c    = lane & 3;

    const float sc = 1.0f + scale[b * HEADS + h];
    const float sh = shift[b * HEADS + h];
    const float qmul = 0.125f;

    uint32_t qh[4][4], ql[4][4];
    {
        int rowA = qt * 64 + wm * 16 + r;
        const float* qA = q + ((size_t)(b * N2 + rowA)) * INNER + h * DH;
        const float* qB = qA + (size_t)8 * INNER;
        #pragma unroll
        for (int ks = 0; ks < 4; ks++) {
            int d0 = ks * 16 + c * 2;
            #pragma unroll
            for (int half = 0; half < 2; half++) {
                float2 vA = *(const float2*)(qA + d0 + half * 8);
                float2 vB = *(const float2*)(qB + d0 + half * 8);
                float ax = (vA.x * sc + sh) * qmul, ay = (vA.y * sc + sh) * qmul;
                float bx = (vB.x * sc + sh) * qmul, by = (vB.y * sc + sh) * qmul;
                float hax = __half2float(__float2half_rn(ax));
                float hay = __half2float(__float2half_rn(ay));
                float hbx = __half2float(__float2half_rn(bx));
                float hby = __half2float(__float2half_rn(by));
                qh[ks][half * 2 + 0] = pack_f16(hax, hay);
                qh[ks][half * 2 + 1] = pack_f16(hbx, hby);
                ql[ks][half * 2 + 0] = pack_f16(ax - hax, ay - hay);
                ql[ks][half * 2 + 1] = pack_f16(bx - hbx, by - hby);
            }
        }
    }

    float o[4][4];
    #pragma unroll
    for (int i = 0; i < 4; i++)
        #pragma unroll
        for (int j = 0; j < 4; j++) o[i][j] = 0.0f;
    float mA = -INFINITY, mB = -INFINITY, lA = 0.0f, lB = 0.0f;

    __half* vS = (__half*)(ash + A_VH);

    for (int kt = 0; kt < N1 / 64; kt++) {
        __syncthreads();

        #pragma unroll
        for (int i = 0; i < 2; i++) {
            int idx = tid + 256 * i;
            int key = idx >> 3;
            int c8  = idx & 7;
            size_t gbase = ((size_t)(b * N1 + kt * 64 + key)) * INNER + h * DH + c8 * 8;
            *(uint4*)(ash + A_KH + key * AST + c8 * 4) = *(const uint4*)(kh + gbase);
            *(uint4*)(ash + A_KL + key * AST + c8 * 4) = *(const uint4*)(kl + gbase);
            uint4 vq = *(const uint4*)(vv + gbase);
            const __half* vp = (const __half*)&vq;
            #pragma unroll
            for (int j = 0; j < 8; j++)
                vS[(c8 * 8 + j) * 72 + key] = vp[j];
        }
        __syncthreads();

        float s[4][4];
        #pragma unroll
        for (int i = 0; i < 4; i++)
            #pragma unroll
            for (int j = 0; j < 4; j++) s[i][j] = 0.0f;

        #pragma unroll
        for (int ks = 0; ks < 4; ks++) {
            #pragma unroll
            for (int atom = 0; atom < 4; atom++) {
                int keyrow = wx * 32 + atom * 8 + r;
                int w = keyrow * AST + c + ks * 8;
                uint32_t bh2[2] = {ash[A_KH + w], ash[A_KH + w + 4]};
                uint32_t bl2[2] = {ash[A_KL + w], ash[A_KL + w + 4]};
                mma_f16(s[atom], qh[ks], bh2);
                mma_f16(s[atom], qh[ks], bl2);
                mma_f16(s[atom], ql[ks], bh2);
            }
        }

        float mxA = s[0][0], mxB = s[0][2];
        #pragma unroll
        for (int atom = 0; atom < 4; atom++) {
            mxA = fmaxf(mxA, fmaxf(s[atom][0], s[atom][1]));
            mxB = fmaxf(mxB, fmaxf(s[atom][2], s[atom][3]));
        }
        mxA = fmaxf(mxA, __shfl_xor_sync(0xffffffffu, mxA, 1));
        mxA = fmaxf(mxA, __shfl_xor_sync(0xffffffffu, mxA, 2));
        mxB = fmaxf(mxB, __shfl_xor_sync(0xffffffffu, mxB, 1));
        mxB = fmaxf(mxB, __shfl_xor_sync(0xffffffffu, mxB, 2));
        if (c == 0) {
            redmax[(wm * 16 + r) * 2 + wx] = mxA;
            redmax[(wm * 16 + r + 8) * 2 + wx] = mxB;
        }
        __syncthreads();

        float mnA = fmaxf(mA, fmaxf(redmax[(wm * 16 + r) * 2],
                                    redmax[(wm * 16 + r) * 2 + 1]));
        float mnB = fmaxf(mB, fmaxf(redmax[(wm * 16 + r + 8) * 2],
                                    redmax[(wm * 16 + r + 8) * 2 + 1]));
        float alphaA = __expf(mA - mnA);
        float alphaB = __expf(mB - mnB);
        mA = mnA; mB = mnB;

        float sumA = 0.0f, sumB = 0.0f;
        #pragma unroll
        for (int atom = 0; atom < 4; atom++) {
            s[atom][0] = __expf(s[atom][0] - mnA);
            s[atom][1] = __expf(s[atom][1] - mnA);
            s[atom][2] = __expf(s[atom][2] - mnB);
            s[atom][3] = __expf(s[atom][3] - mnB);
            sumA += s[atom][0] + s[atom][1];
            sumB += s[atom][2] + s[atom][3];
        }
        sumA += __shfl_xor_sync(0xffffffffu, sumA, 1);
        sumA += __shfl_xor_sync(0xffffffffu, sumA, 2);
        sumB += __shfl_xor_sync(0xffffffffu, sumB, 1);
        sumB += __shfl_xor_sync(0xffffffffu, sumB, 2);
        if (c == 0) {
            redsum[(wm * 16 + r) * 2 + wx] = sumA;
            redsum[(wm * 16 + r + 8) * 2 + wx] = sumB;
        }

        #pragma unroll
        for (int atom = 0; atom < 4; atom++) {
            int wpos = wx * 16 + atom * 4 + c;
            ash[A_PH + (wm * 16 + r) * AST + wpos]     = pack_f16(s[atom][0], s[atom][1]);
            ash[A_PH + (wm * 16 + r + 8) * AST + wpos] = pack_f16(s[atom][2], s[atom][3]);
            o[atom][0] *= alphaA; o[atom][1] *= alphaA;
            o[atom][2] *= alphaB; o[atom][3] *= alphaB;
        }
        __syncthreads();

        lA = lA * alphaA + redsum[(wm * 16 + r) * 2] + redsum[(wm * 16 + r) * 2 + 1];
        lB = lB * alphaB + redsum[(wm * 16 + r + 8) * 2] + redsum[(wm * 16 + r + 8) * 2 + 1];

        #pragma unroll
        for (int ks = 0; ks < 4; ks++) {
            int row0 = wm * 16 + r;
            int wb = ks * 8 + c;
            uint32_t a2[4];
            a2[0] = ash[A_PH + row0 * AST + wb];
            a2[1] = ash[A_PH + (row0 + 8) * AST + wb];
            a2[2] = ash[A_PH + row0 * AST + wb + 4];
            a2[3] = ash[A_PH + (row0 + 8) * AST + wb + 4];
            #pragma unroll
            for (int atom = 0; atom < 4; atom++) {
                int drow = wx * 32 + atom * 8 + r;
                int w = drow * AST + c + ks * 8;
                uint32_t b2[2] = {ash[A_VH + w], ash[A_VH + w + 4]};
                mma_f16(o[atom], a2, b2);
            }
        }
    }

    float invA = 1.0f / lA, invB = 1.0f / lB;
    int rowA = qt * 64 + wm * 16 + r;
    uint32_t* o32 = (uint32_t*)outp;
    #pragma unroll
    for (int atom = 0; atom < 4; atom++) {
        int col = h * DH + wx * 32 + atom * 8 + c * 2;
        size_t iA = (((size_t)(b * N2 + rowA)) * INNER + col) >> 1;
        size_t iB = (((size_t)(b * N2 + rowA + 8)) * INNER + col) >> 1;
        o32[iA] = pack_f16(o[atom][0] * invA, o[atom][1] * invA);
        o32[iB] = pack_f16(o[atom][2] * invB, o[atom][3] * invB);
    }
}

// ---------------------------------------------------------------------------
// Launcher. K-GEMM stays in ncu slot 4.
// ---------------------------------------------------------------------------
extern "C" void kernel_launch(void* const* d_in, const int* in_sizes, int n_in,
                              void* d_out, int out_size) {
    const float* x       = (const float*)d_in[0];
    const float* latents = (const float*)d_in[1];
    const float* shift   = (const float*)d_in[2];
    const float* scale   = (const float*)d_in[3];
    const float* ln1_w   = (const float*)d_in[4];
    const float* ln1_b   = (const float*)d_in[5];
    const float* ln2_w   = (const float*)d_in[6];
    const float* ln2_b   = (const float*)d_in[7];
    const float* Wq      = (const float*)d_in[8];
    const float* Wkv     = (const float*)d_in[9];
    const float* Wout    = (const float*)d_in[10];
    float* out           = (float*)d_out;

    __half *xnh, *xnl, *lnh, *lnl, *wqTh, *wqTl, *wkvTh, *wkvTl, *woTh, *woTl;
    __half *kH, *kL, *v, *ao;
    float *q;
    cudaGetSymbolAddress((void**)&xnh,   g_xnh);
    cudaGetSymbolAddress((void**)&xnl,   g_xnl);
    cudaGetSymbolAddress((void**)&lnh,   g_lnh);
    cudaGetSymbolAddress((void**)&lnl,   g_lnl);
    cudaGetSymbolAddress((void**)&wqTh,  g_wqTh);
    cudaGetSymbolAddress((void**)&wqTl,  g_wqTl);
    cudaGetSymbolAddress((void**)&wkvTh, g_wkvTh);
    cudaGetSymbolAddress((void**)&wkvTl, g_wkvTl);
    cudaGetSymbolAddress((void**)&woTh,  g_woTh);
    cudaGetSymbolAddress((void**)&woTl,  g_woTl);
    cudaGetSymbolAddress((void**)&kH,    g_kh);
    cudaGetSymbolAddress((void**)&kL,    g_kl);
    cudaGetSymbolAddress((void**)&v,     g_v);
    cudaGetSymbolAddress((void**)&ao,    g_ao);
    cudaGetSymbolAddress((void**)&q,     g_q);

    cudaFuncSetAttribute(gemm3_kernel,
                         cudaFuncAttributeMaxDynamicSharedMemorySize, G3_SMEM);
    cudaFuncSetAttribute(gemm2_kernel,
                         cudaFuncAttributeMaxDynamicSharedMemorySize, G2_SMEM);
    cudaFuncSetAttribute(attn_tc_kernel,
                         cudaFuncAttributeMaxDynamicSharedMemorySize, ATT_SMEM);

    // 1) LN(x) -> split fp16
    ln_split_kernel<<<BSZ * N1, 256>>>(x, ln1_w, ln1_b, xnh, xnl);
    // 2) Wkv^T split
    transpose_split_kernel<<<dim3(2 * INNER / 32, DIM / 32), dim3(32, 8)>>>(
        Wkv, wkvTh, wkvTl, DIM, 2 * INNER);
    // 3) LN(latents)
    ln_split_kernel<<<BSZ * N2, 256>>>(latents, ln2_w, ln2_b, lnh, lnl);

    // 4) K-GEMM (3-term, split fp16 out) — profiled slot
    gemm3_kernel<<<dim3(INNER / 128, (BSZ * N1) / 128), 256, G3_SMEM>>>(
        xnh, xnl, wkvTh, wkvTl, nullptr, kH, kL, BSZ * N1, INNER, DIM, 1);

    // 5) V-GEMM (2-term, single fp16 out)
    gemm2_kernel<<<dim3(INNER / 128, (BSZ * N1) / 128), 256, G2_SMEM>>>(
        xnh, wkvTh + (size_t)INNER * DIM, wkvTl + (size_t)INNER * DIM,
        nullptr, v, BSZ * N1, INNER, DIM, 1);

    // 6-7) remaining weight transposes
    transpose_split_kernel<<<dim3(INNER / 32, DIM / 32), dim3(32, 8)>>>(
        Wq, wqTh, wqTl, DIM, INNER);
    transpose_split_kernel<<<dim3(DIM / 32, INNER / 32), dim3(32, 8)>>>(
        Wout, woTh, woTl, INNER, DIM);

    // 8) q-GEMM (3-term, fp32 out)
    gemm3_kernel<<<dim3(INNER / 128, (BSZ * N2) / 128), 256, G3_SMEM>>>(
        lnh, lnl, wqTh, wqTl, q, nullptr, nullptr, BSZ * N2, INNER, DIM, 0);

    // 9) attention (S 3-term, PV 1-term)
    attn_tc_kernel<<<dim3(BSZ * HEADS, N2 / 64), 256, ATT_SMEM>>>(
        q, kH, kL, v, shift, scale, ao);

    // 10) out-GEMM (2-term, fp32 out)
    gemm2_kernel<<<dim3(DIM / 128, (BSZ * N2) / 128), 256, G2_SMEM>>>(
        ao, woTh, woTl, out, nullptr, BSZ * N2, DIM, INNER, 0);
}

// round 14
// speedup vs baseline: 1.0971x; 1.0971x over previous
#include <cuda_runtime.h>
#include <cuda_fp16.h>
#include <cstdint>
#include <math.h>

// Problem constants
#define BSZ   4
#define N1    4096
#define N2    256
#define DIM   1024
#define HEADS 16
#define DH    64
#define INNER 1024
#define EPS   1e-5f

// ---------------------------------------------------------------------------
// Scratch (device globals). fp16 (hi, lo) pairs where the softmax path needs
// near-fp32 precision; single fp16 on the unamplified V/P/ao path.
// ---------------------------------------------------------------------------
__device__ __half g_xnh[BSZ * N1 * DIM];
__device__ __half g_xnl[BSZ * N1 * DIM];
__device__ __half g_lnh[BSZ * N2 * DIM];
__device__ __half g_lnl[BSZ * N2 * DIM];
__device__ __half g_wqTh[INNER * DIM];
__device__ __half g_wqTl[INNER * DIM];
__device__ __half g_wkvTh[2 * INNER * DIM];
__device__ __half g_wkvTl[2 * INNER * DIM];
__device__ __half g_woTh[DIM * INNER];
__device__ __half g_woTl[DIM * INNER];
__device__ __half g_kh[BSZ * N1 * INNER];
__device__ __half g_kl[BSZ * N1 * INNER];
__device__ __half g_v [BSZ * N1 * INNER];
__device__ __half g_ao[BSZ * N2 * INNER];
__device__ float  g_q [BSZ * N2 * INNER];

// ---------------------------------------------------------------------------
// Helpers
// ---------------------------------------------------------------------------
__device__ __forceinline__ void mma_f16(float* c, const uint32_t* a, const uint32_t* b) {
    asm volatile(
        "mma.sync.aligned.m16n8k16.row.col.f32.f16.f16.f32 "
        "{%0,%1,%2,%3}, {%4,%5,%6,%7}, {%8,%9}, {%0,%1,%2,%3};"
        : "+f"(c[0]), "+f"(c[1]), "+f"(c[2]), "+f"(c[3])
        : "r"(a[0]), "r"(a[1]), "r"(a[2]), "r"(a[3]), "r"(b[0]), "r"(b[1]));
}

__device__ __forceinline__ void ldsm4(uint32_t* r, uint32_t addr) {
    asm volatile("ldmatrix.sync.aligned.m8n8.x4.shared.b16 {%0,%1,%2,%3}, [%4];"
                 : "=r"(r[0]), "=r"(r[1]), "=r"(r[2]), "=r"(r[3]) : "r"(addr));
}

__device__ __forceinline__ void ldsm2(uint32_t* r, uint32_t addr) {
    asm volatile("ldmatrix.sync.aligned.m8n8.x2.shared.b16 {%0,%1}, [%2];"
                 : "=r"(r[0]), "=r"(r[1]) : "r"(addr));
}

__device__ __forceinline__ uint32_t pack_f16(float x, float y) {
    __half2 h = __floats2half2_rn(x, y);
    return *reinterpret_cast<uint32_t*>(&h);
}

__device__ __forceinline__ uint32_t smem_u32p(const void* p) {
    uint32_t a;
    asm("{ .reg .u64 t; cvta.to.shared.u64 t, %1; cvt.u32.u64 %0, t; }" : "=r"(a) : "l"(p));
    return a;
}

__device__ __forceinline__ void cp16(uint32_t dst, const void* src) {
    asm volatile("cp.async.cg.shared.global [%0], [%1], 16;" :: "r"(dst), "l"(src));
}

__device__ __forceinline__ float block_sum_256(float v, float* sbuf) {
    #pragma unroll
    for (int off = 16; off > 0; off >>= 1)
        v += __shfl_xor_sync(0xffffffffu, v, off);
    int w = threadIdx.x >> 5;
    if ((threadIdx.x & 31) == 0) sbuf[w] = v;
    __syncthreads();
    float r = (threadIdx.x < 8) ? sbuf[threadIdx.x] : 0.0f;
    #pragma unroll
    for (int off = 4; off > 0; off >>= 1)
        r += __shfl_xor_sync(0xffffffffu, r, off);
    if (threadIdx.x == 0) sbuf[0] = r;
    __syncthreads();
    float out = sbuf[0];
    __syncthreads();
    return out;
}

// ---------------------------------------------------------------------------
// LayerNorm (row of 1024) -> split fp16 hi/lo outputs.
// ---------------------------------------------------------------------------
__global__ void ln_split_kernel(const float* __restrict__ x,
                                const float* __restrict__ w,
                                const float* __restrict__ b,
                                __half* __restrict__ yh,
                                __half* __restrict__ yl) {
    __shared__ float sbuf[8];
    size_t row = blockIdx.x;
    int t = threadIdx.x;

    const float4 v = ((const float4*)(x + row * DIM))[t];
    float s = v.x + v.y + v.z + v.w;
    float tot = block_sum_256(s, sbuf);
    float mean = tot * (1.0f / DIM);

    float dx = v.x - mean, dy = v.y - mean, dz = v.z - mean, dw = v.w - mean;
    float sq = dx * dx + dy * dy + dz * dz + dw * dw;
    float vtot = block_sum_256(sq, sbuf);
    float inv = rsqrtf(vtot * (1.0f / DIM) + EPS);

    const float4 wv = ((const float4*)w)[t];
    const float4 bv = ((const float4*)b)[t];
    float o0 = dx * inv * wv.x + bv.x;
    float o1 = dy * inv * wv.y + bv.y;
    float o2 = dz * inv * wv.z + bv.z;
    float o3 = dw * inv * wv.w + bv.w;

    float h0 = __half2float(__float2half_rn(o0));
    float h1 = __half2float(__float2half_rn(o1));
    float h2 = __half2float(__float2half_rn(o2));
    float h3 = __half2float(__float2half_rn(o3));

    ((uint2*)(yh + row * DIM))[t] = make_uint2(pack_f16(h0, h1), pack_f16(h2, h3));
    ((uint2*)(yl + row * DIM))[t] = make_uint2(pack_f16(o0 - h0, o1 - h1),
                                               pack_f16(o2 - h2, o3 - h3));
}

// ---------------------------------------------------------------------------
// 32x32 tiled transpose with fp16 hi/lo split
// ---------------------------------------------------------------------------
__global__ void transpose_split_kernel(const float* __restrict__ in,
                                       __half* __restrict__ outh,
                                       __half* __restrict__ outl,
                                       int R, int C) {
    __shared__ float t[32][33];
    int c0 = blockIdx.x * 32, r0 = blockIdx.y * 32;
    #pragma unroll
    for (int i = 0; i < 32; i += 8)
        t[threadIdx.y + i][threadIdx.x] =
            in[(size_t)(r0 + threadIdx.y + i) * C + c0 + threadIdx.x];
    __syncthreads();
    #pragma unroll
    for (int i = 0; i < 32; i += 8) {
        float v = t[threadIdx.x][threadIdx.y + i];
        __half h = __float2half_rn(v);
        size_t idx = (size_t)(c0 + threadIdx.y + i) * R + r0 + threadIdx.x;
        outh[idx] = h;
        outl[idx] = __float2half_rn(v - __half2float(h));
    }
}

// ---------------------------------------------------------------------------
// 3-term fp16 GEMM (both operands split pairs):
//   C = Ah·Bh^T + Ah·Bl^T + Al·Bh^T
// R10 pipeline structure (2-stage cp.async double buffer, 2 CTAs/SM),
// ldmatrix fragment loads (bank-conflict-free on stride-20 layout).
// ---------------------------------------------------------------------------
#define RS 20
#define MATW (128 * RS)
#define ST3_W (4 * MATW)
#define G3_SMEM (2 * ST3_W * 4)         // 81920 B

__global__ void __launch_bounds__(256, 2)
gemm3_kernel(const __half* __restrict__ Ah, const __half* __restrict__ Al,
             const __half* __restrict__ Bh, const __half* __restrict__ Bl,
             float* __restrict__ C, __half* __restrict__ Ch, __half* __restrict__ Cl,
             int M, int N, int K, int split_out) {
    extern __shared__ uint32_t sh[];
    const uint32_t sbase = smem_u32p(sh);

    const int tid  = threadIdx.x;
    const int lane = tid & 31;
    const int wid  = tid >> 5;
    const int warp_m = wid >> 2;
    const int warp_n = wid & 3;
    const int bm = blockIdx.y * 128;
    const int bn = blockIdx.x * 128;

    const int matB = tid >> 7;
    const int lt   = tid & 127;
    const int lf   = lt & 3;
    const int lr0  = lt >> 2;
    const __half* srcH = matB ? (Bh + (size_t)bn * K) : (Ah + (size_t)bm * K);
    const __half* srcL = matB ? (Bl + (size_t)bn * K) : (Al + (size_t)bm * K);
    const uint32_t dH_bytes = (matB ? 2 * MATW : 0) * 4;
    const uint32_t dL_bytes = dH_bytes + MATW * 4;

    // ldmatrix address offsets (bytes, within stage)
    const uint32_t arow_off =
        ((uint32_t)(warp_m * 64 + (lane & 7) + ((lane >> 3) & 1) * 8) * RS
         + (uint32_t)(lane >> 4) * 4) * 4;
    const uint32_t brow_off =
        ((uint32_t)(warp_n * 32 + (lane & 7)) * RS
         + (uint32_t)((lane >> 3) & 1) * 4) * 4;

    float acc[4][4][4];
    #pragma unroll
    for (int i = 0; i < 4; i++)
        #pragma unroll
        for (int j = 0; j < 4; j++)
            #pragma unroll
            for (int k = 0; k < 4; k++) acc[i][j][k] = 0.0f;

    const int S = K >> 5;

    // prologue: stages 0 and 1
    #pragma unroll
    for (int pre = 0; pre < 2; pre++) {
        uint32_t stbase = sbase + (uint32_t)(pre * ST3_W * 4);
        #pragma unroll
        for (int i = 0; i < 4; i++) {
            int row = lr0 + 32 * i;
            uint32_t doff = (uint32_t)((row * RS + lf * 4) * 4);
            cp16(stbase + dH_bytes + doff, srcH + (size_t)row * K + pre * 32 + lf * 8);
            cp16(stbase + dL_bytes + doff, srcL + (size_t)row * K + pre * 32 + lf * 8);
        }
        asm volatile("cp.async.commit_group;" ::: "memory");
    }

    for (int s = 0; s < S; s++) {
        asm volatile("cp.async.wait_group 1;" ::: "memory");
        __syncthreads();

        const uint32_t stb = sbase + (uint32_t)((s & 1) * ST3_W * 4);
        const uint32_t aAH = stb + arow_off;
        const uint32_t bBH = stb + 2 * MATW * 4 + brow_off;

        #pragma unroll
        for (int ks = 0; ks < 2; ks++) {
            uint32_t bh[4][2], bl[4][2];
            #pragma unroll
            for (int nb = 0; nb < 4; nb++) {
                uint32_t ba = bBH + nb * (8 * RS * 4) + ks * 32;
                ldsm2(bh[nb], ba);
                ldsm2(bl[nb], ba + MATW * 4);
            }
            #pragma unroll
            for (int ma = 0; ma < 4; ma++) {
                uint32_t aa = aAH + ma * (16 * RS * 4) + ks * 32;
                uint32_t ah[4], al[4];
                ldsm4(ah, aa);
                ldsm4(al, aa + MATW * 4);
                #pragma unroll
                for (int nb = 0; nb < 4; nb++) {
                    mma_f16(acc[ma][nb], ah, bh[nb]);
                    mma_f16(acc[ma][nb], ah, bl[nb]);
                    mma_f16(acc[ma][nb], al, bh[nb]);
                }
            }
        }
        __syncthreads();

        if (s + 2 < S) {
            int k0 = (s + 2) * 32;
            uint32_t stbase = sbase + (uint32_t)((s & 1) * ST3_W * 4);
            #pragma unroll
            for (int i = 0; i < 4; i++) {
                int row = lr0 + 32 * i;
                uint32_t doff = (uint32_t)((row * RS + lf * 4) * 4);
                cp16(stbase + dH_bytes + doff, srcH + (size_t)row * K + k0 + lf * 8);
                cp16(stbase + dL_bytes + doff, srcL + (size_t)row * K + k0 + lf * 8);
            }
        }
        asm volatile("cp.async.commit_group;" ::: "memory");
    }

    uint32_t* Hh = (uint32_t*)Ch;
    uint32_t* Hl = (uint32_t*)Cl;
    #pragma unroll
    for (int ma = 0; ma < 4; ma++) {
        int row = bm + warp_m * 64 + ma * 16 + (lane >> 2);
        #pragma unroll
        for (int nb = 0; nb < 4; nb++) {
            int col = bn + warp_n * 32 + nb * 8 + (lane & 3) * 2;
            if (split_out) {
                float v0 = acc[ma][nb][0], v1 = acc[ma][nb][1];
                float v2 = acc[ma][nb][2], v3 = acc[ma][nb][3];
                float h0 = __half2float(__float2half_rn(v0));
                float h1 = __half2float(__float2half_rn(v1));
                float h2 = __half2float(__float2half_rn(v2));
                float h3 = __half2float(__float2half_rn(v3));
                size_t i0 = ((size_t)row * N + col) >> 1;
                size_t i1 = ((size_t)(row + 8) * N + col) >> 1;
                Hh[i0] = pack_f16(h0, h1);
                Hl[i0] = pack_f16(v0 - h0, v1 - h1);
                Hh[i1] = pack_f16(h2, h3);
                Hl[i1] = pack_f16(v2 - h2, v3 - h3);
            } else {
                *(float2*)(C + (size_t)row * N + col) =
                    make_float2(acc[ma][nb][0], acc[ma][nb][1]);
                *(float2*)(C + (size_t)(row + 8) * N + col) =
                    make_float2(acc[ma][nb][2], acc[ma][nb][3]);
            }
        }
    }
}

// ---------------------------------------------------------------------------
// 2-term fp16 GEMM (A single, B split pair): C = A·Bh^T + A·Bl^T
// R10 pipeline structure + ldmatrix fragment loads.
// ---------------------------------------------------------------------------
#define ST2_W (3 * MATW)
#define G2_SMEM (2 * ST2_W * 4)         // 61440 B

__global__ void __launch_bounds__(256, 2)
gemm2_kernel(const __half* __restrict__ A,
             const __half* __restrict__ Bh, const __half* __restrict__ Bl,
             float* __restrict__ C, __half* __restrict__ Ch,
             int M, int N, int K, int half_out) {
    extern __shared__ uint32_t sh[];
    const uint32_t sbase = smem_u32p(sh);

    const int tid  = threadIdx.x;
    const int lane = tid & 31;
    const int wid  = tid >> 5;
    const int warp_m = wid >> 2;
    const int warp_n = wid & 3;
    const int bm = blockIdx.y * 128;
    const int bn = blockIdx.x * 128;

    const int matB = tid >> 7;
    const int lt   = tid & 127;
    const int lf   = lt & 3;
    const int lr0  = lt >> 2;
    const __half* srcA  = A  + (size_t)bm * K;
    const __half* srcBh = Bh + (size_t)bn * K;
    const __half* srcBl = Bl + (size_t)bn * K;

    const uint32_t arow_off =
        ((uint32_t)(warp_m * 64 + (lane & 7) + ((lane >> 3) & 1) * 8) * RS
         + (uint32_t)(lane >> 4) * 4) * 4;
    const uint32_t brow_off =
        ((uint32_t)(warp_n * 32 + (lane & 7)) * RS
         + (uint32_t)((lane >> 3) & 1) * 4) * 4;

    float acc[4][4][4];
    #pragma unroll
    for (int i = 0; i < 4; i++)
        #pragma unroll
        for (int j = 0; j < 4; j++)
            #pragma unroll
            for (int k = 0; k < 4; k++) acc[i][j][k] = 0.0f;

    const int S = K >> 5;

    #pragma unroll
    for (int pre = 0; pre < 2; pre++) {
        uint32_t stbase = sbase + (uint32_t)(pre * ST2_W * 4);
        #pragma unroll
        for (int i = 0; i < 4; i++) {
            int row = lr0 + 32 * i;
            uint32_t doff = (uint32_t)((row * RS + lf * 4) * 4);
            if (matB == 0) {
                cp16(stbase + doff, srcA + (size_t)row * K + pre * 32 + lf * 8);
            } else {
                cp16(stbase + MATW * 4 + doff,     srcBh + (size_t)row * K + pre * 32 + lf * 8);
                cp16(stbase + 2 * MATW * 4 + doff, srcBl + (size_t)row * K + pre * 32 + lf * 8);
            }
        }
        asm volatile("cp.async.commit_group;" ::: "memory");
    }

    for (int s = 0; s < S; s++) {
        asm volatile("cp.async.wait_group 1;" ::: "memory");
        __syncthreads();

        const uint32_t stb = sbase + (uint32_t)((s & 1) * ST2_W * 4);
        const uint32_t aA  = stb + arow_off;
        const uint32_t bBH = stb + MATW * 4 + brow_off;

        #pragma unroll
        for (int ks = 0; ks < 2; ks++) {
            uint32_t bh[4][2], bl[4][2];
            #pragma unroll
            for (int nb = 0; nb < 4; nb++) {
                uint32_t ba = bBH + nb * (8 * RS * 4) + ks * 32;
                ldsm2(bh[nb], ba);
                ldsm2(bl[nb], ba + MATW * 4);
            }
            #pragma unroll
            for (int ma = 0; ma < 4; ma++) {
                uint32_t a[4];
                ldsm4(a, aA + ma * (16 * RS * 4) + ks * 32);
                #pragma unroll
                for (int nb = 0; nb < 4; nb++) {
                    mma_f16(acc[ma][nb], a, bh[nb]);
                    mma_f16(acc[ma][nb], a, bl[nb]);
                }
            }
        }
        __syncthreads();

        if (s + 2 < S) {
            int k0 = (s + 2) * 32;
            uint32_t stbase = sbase + (uint32_t)((s & 1) * ST2_W * 4);
            #pragma unroll
            for (int i = 0; i < 4; i++) {
                int row = lr0 + 32 * i;
                uint32_t doff = (uint32_t)((row * RS + lf * 4) * 4);
                if (matB == 0) {
                    cp16(stbase + doff, srcA + (size_t)row * K + k0 + lf * 8);
                } else {
                    cp16(stbase + MATW * 4 + doff,     srcBh + (size_t)row * K + k0 + lf * 8);
                    cp16(stbase + 2 * MATW * 4 + doff, srcBl + (size_t)row * K + k0 + lf * 8);
                }
            }
        }
        asm volatile("cp.async.commit_group;" ::: "memory");
    }

    uint32_t* H = (uint32_t*)Ch;
    #pragma unroll
    for (int ma = 0; ma < 4; ma++) {
        int row = bm + warp_m * 64 + ma * 16 + (lane >> 2);
        #pragma unroll
        for (int nb = 0; nb < 4; nb++) {
            int col = bn + warp_n * 32 + nb * 8 + (lane & 3) * 2;
            if (half_out) {
                H[((size_t)row * N + col) >> 1] =
                    pack_f16(acc[ma][nb][0], acc[ma][nb][1]);
                H[((size_t)(row + 8) * N + col) >> 1] =
                    pack_f16(acc[ma][nb][2], acc[ma][nb][3]);
            } else {
                *(float2*)(C + (size_t)row * N + col) =
                    make_float2(acc[ma][nb][0], acc[ma][nb][1]);
                *(float2*)(C + (size_t)(row + 8) * N + col) =
                    make_float2(acc[ma][nb][2], acc[ma][nb][3]);
            }
        }
    }
}

// ---------------------------------------------------------------------------
// Tensor-core flash attention per (b, h, 64-query tile).  (unchanged)
// ---------------------------------------------------------------------------
#define AST 36
#define AMAT (64 * AST)
#define A_KH 0
#define A_KL (AMAT)
#define A_VH (2 * AMAT)
#define A_PH (3 * AMAT)
#define A_RED (4 * AMAT)
#define ATT_SMEM ((4 * AMAT + 256) * 4)

__global__ void __launch_bounds__(256, 2)
attn_tc_kernel(const float* __restrict__ q,
               const __half* __restrict__ kh,
               const __half* __restrict__ kl,
               const __half* __restrict__ vv,
               const float* __restrict__ shift,
               const float* __restrict__ scale,
               __half* __restrict__ outp) {
    extern __shared__ uint32_t ash[];
    float* redmax = (float*)(ash + A_RED);
    float* redsum = redmax + 128;

    const int bh = blockIdx.x;
    const int b  = bh >> 4;
    const int h  = bh & 15;
    const int qt = blockIdx.y;

    const int tid  = threadIdx.x;
    const int lane = tid & 31;
    const int wid  = tid >> 5;
    const int wm   = wid >> 1;
    const int wx   = wid & 1;
    const int r    = lane >> 2;
    const int c    = lane & 3;

    const float sc = 1.0f + scale[b * HEADS + h];
    const float sh = shift[b * HEADS + h];
    const float qmul = 0.125f;

    uint32_t qh[4][4], ql[4][4];
    {
        int rowA = qt * 64 + wm * 16 + r;
        const float* qA = q + ((size_t)(b * N2 + rowA)) * INNER + h * DH;
        const float* qB = qA + (size_t)8 * INNER;
        #pragma unroll
        for (int ks = 0; ks < 4; ks++) {
            int d0 = ks * 16 + c * 2;
            #pragma unroll
            for (int half = 0; half < 2; half++) {
                float2 vA = *(const float2*)(qA + d0 + half * 8);
                float2 vB = *(const float2*)(qB + d0 + half * 8);
                float ax = (vA.x * sc + sh) * qmul, ay = (vA.y * sc + sh) * qmul;
                float bx = (vB.x * sc + sh) * qmul, by = (vB.y * sc + sh) * qmul;
                float hax = __half2float(__float2half_rn(ax));
                float hay = __half2float(__float2half_rn(ay));
                float hbx = __half2float(__float2half_rn(bx));
                float hby = __half2float(__float2half_rn(by));
                qh[ks][half * 2 + 0] = pack_f16(hax, hay);
                qh[ks][half * 2 + 1] = pack_f16(hbx, hby);
                ql[ks][half * 2 + 0] = pack_f16(ax - hax, ay - hay);
                ql[ks][half * 2 + 1] = pack_f16(bx - hbx, by - hby);
            }
        }
    }

    float o[4][4];
    #pragma unroll
    for (int i = 0; i < 4; i++)
        #pragma unroll
        for (int j = 0; j < 4; j++) o[i][j] = 0.0f;
    float mA = -INFINITY, mB = -INFINITY, lA = 0.0f, lB = 0.0f;

    __half* vS = (__half*)(ash + A_VH);

    for (int kt = 0; kt < N1 / 64; kt++) {
        __syncthreads();

        #pragma unroll
        for (int i = 0; i < 2; i++) {
            int idx = tid + 256 * i;
            int key = idx >> 3;
            int c8  = idx & 7;
            size_t gbase = ((size_t)(b * N1 + kt * 64 + key)) * INNER + h * DH + c8 * 8;
            *(uint4*)(ash + A_KH + key * AST + c8 * 4) = *(const uint4*)(kh + gbase);
            *(uint4*)(ash + A_KL + key * AST + c8 * 4) = *(const uint4*)(kl + gbase);
            uint4 vq = *(const uint4*)(vv + gbase);
            const __half* vp = (const __half*)&vq;
            #pragma unroll
            for (int j = 0; j < 8; j++)
                vS[(c8 * 8 + j) * 72 + key] = vp[j];
        }
        __syncthreads();

        float s[4][4];
        #pragma unroll
        for (int i = 0; i < 4; i++)
            #pragma unroll
            for (int j = 0; j < 4; j++) s[i][j] = 0.0f;

        #pragma unroll
        for (int ks = 0; ks < 4; ks++) {
            #pragma unroll
            for (int atom = 0; atom < 4; atom++) {
                int keyrow = wx * 32 + atom * 8 + r;
                int w = keyrow * AST + c + ks * 8;
                uint32_t bh2[2] = {ash[A_KH + w], ash[A_KH + w + 4]};
                uint32_t bl2[2] = {ash[A_KL + w], ash[A_KL + w + 4]};
                mma_f16(s[atom], qh[ks], bh2);
                mma_f16(s[atom], qh[ks], bl2);
                mma_f16(s[atom], ql[ks], bh2);
            }
        }

        float mxA = s[0][0], mxB = s[0][2];
        #pragma unroll
        for (int atom = 0; atom < 4; atom++) {
            mxA = fmaxf(mxA, fmaxf(s[atom][0], s[atom][1]));
            mxB = fmaxf(mxB, fmaxf(s[atom][2], s[atom][3]));
        }
        mxA = fmaxf(mxA, __shfl_xor_sync(0xffffffffu, mxA, 1));
        mxA = fmaxf(mxA, __shfl_xor_sync(0xffffffffu, mxA, 2));
        mxB = fmaxf(mxB, __shfl_xor_sync(0xffffffffu, mxB, 1));
        mxB = fmaxf(mxB, __shfl_xor_sync(0xffffffffu, mxB, 2));
        if (c == 0) {
            redmax[(wm * 16 + r) * 2 + wx] = mxA;
            redmax[(wm * 16 + r + 8) * 2 + wx] = mxB;
        }
        __syncthreads();

        float mnA = fmaxf(mA, fmaxf(redmax[(wm * 16 + r) * 2],
                                    redmax[(wm * 16 + r) * 2 + 1]));
        float mnB = fmaxf(mB, fmaxf(redmax[(wm * 16 + r + 8) * 2],
                                    redmax[(wm * 16 + r + 8) * 2 + 1]));
        float alphaA = __expf(mA - mnA);
        float alphaB = __expf(mB - mnB);
        mA = mnA; mB = mnB;

        float sumA = 0.0f, sumB = 0.0f;
        #pragma unroll
        for (int atom = 0; atom < 4; atom++) {
            s[atom][0] = __expf(s[atom][0] - mnA);
            s[atom][1] = __expf(s[atom][1] - mnA);
            s[atom][2] = __expf(s[atom][2] - mnB);
            s[atom][3] = __expf(s[atom][3] - mnB);
            sumA += s[atom][0] + s[atom][1];
            sumB += s[atom][2] + s[atom][3];
        }
        sumA += __shfl_xor_sync(0xffffffffu, sumA, 1);
        sumA += __shfl_xor_sync(0xffffffffu, sumA, 2);
        sumB += __shfl_xor_sync(0xffffffffu, sumB, 1);
        sumB += __shfl_xor_sync(0xffffffffu, sumB, 2);
        if (c == 0) {
            redsum[(wm * 16 + r) * 2 + wx] = sumA;
            redsum[(wm * 16 + r + 8) * 2 + wx] = sumB;
        }

        #pragma unroll
        for (int atom = 0; atom < 4; atom++) {
            int wpos = wx * 16 + atom * 4 + c;
            ash[A_PH + (wm * 16 + r) * AST + wpos]     = pack_f16(s[atom][0], s[atom][1]);
            ash[A_PH + (wm * 16 + r + 8) * AST + wpos] = pack_f16(s[atom][2], s[atom][3]);
            o[atom][0] *= alphaA; o[atom][1] *= alphaA;
            o[atom][2] *= alphaB; o[atom][3] *= alphaB;
        }
        __syncthreads();

        lA = lA * alphaA + redsum[(wm * 16 + r) * 2] + redsum[(wm * 16 + r) * 2 + 1];
        lB = lB * alphaB + redsum[(wm * 16 + r + 8) * 2] + redsum[(wm * 16 + r + 8) * 2 + 1];

        #pragma unroll
        for (int ks = 0; ks < 4; ks++) {
            int row0 = wm * 16 + r;
            int wb = ks * 8 + c;
            uint32_t a2[4];
            a2[0] = ash[A_PH + row0 * AST + wb];
            a2[1] = ash[A_PH + (row0 + 8) * AST + wb];
            a2[2] = ash[A_PH + row0 * AST + wb + 4];
            a2[3] = ash[A_PH + (row0 + 8) * AST + wb + 4];
            #pragma unroll
            for (int atom = 0; atom < 4; atom++) {
                int drow = wx * 32 + atom * 8 + r;
                int w = drow * AST + c + ks * 8;
                uint32_t b2[2] = {ash[A_VH + w], ash[A_VH + w + 4]};
                mma_f16(o[atom], a2, b2);
            }
        }
    }

    float invA = 1.0f / lA, invB = 1.0f / lB;
    int rowA = qt * 64 + wm * 16 + r;
    uint32_t* o32 = (uint32_t*)outp;
    #pragma unroll
    for (int atom = 0; atom < 4; atom++) {
        int col = h * DH + wx * 32 + atom * 8 + c * 2;
        size_t iA = (((size_t)(b * N2 + rowA)) * INNER + col) >> 1;
        size_t iB = (((size_t)(b * N2 + rowA + 8)) * INNER + col) >> 1;
        o32[iA] = pack_f16(o[atom][0] * invA, o[atom][1] * invA);
        o32[iB] = pack_f16(o[atom][2] * invB, o[atom][3] * invB);
    }
}

// ---------------------------------------------------------------------------
// Launcher. K-GEMM stays in ncu slot 4.
// ---------------------------------------------------------------------------
extern "C" void kernel_launch(void* const* d_in, const int* in_sizes, int n_in,
                              void* d_out, int out_size) {
    const float* x       = (const float*)d_in[0];
    const float* latents = (const float*)d_in[1];
    const float* shift   = (const float*)d_in[2];
    const float* scale   = (const float*)d_in[3];
    const float* ln1_w   = (const float*)d_in[4];
    const float* ln1_b   = (const float*)d_in[5];
    const float* ln2_w   = (const float*)d_in[6];
    const float* ln2_b   = (const float*)d_in[7];
    const float* Wq      = (const float*)d_in[8];
    const float* Wkv     = (const float*)d_in[9];
    const float* Wout    = (const float*)d_in[10];
    float* out           = (float*)d_out;

    __half *xnh, *xnl, *lnh, *lnl, *wqTh, *wqTl, *wkvTh, *wkvTl, *woTh, *woTl;
    __half *kH, *kL, *v, *ao;
    float *q;
    cudaGetSymbolAddress((void**)&xnh,   g_xnh);
    cudaGetSymbolAddress((void**)&xnl,   g_xnl);
    cudaGetSymbolAddress((void**)&lnh,   g_lnh);
    cudaGetSymbolAddress((void**)&lnl,   g_lnl);
    cudaGetSymbolAddress((void**)&wqTh,  g_wqTh);
    cudaGetSymbolAddress((void**)&wqTl,  g_wqTl);
    cudaGetSymbolAddress((void**)&wkvTh, g_wkvTh);
    cudaGetSymbolAddress((void**)&wkvTl, g_wkvTl);
    cudaGetSymbolAddress((void**)&woTh,  g_woTh);
    cudaGetSymbolAddress((void**)&woTl,  g_woTl);
    cudaGetSymbolAddress((void**)&kH,    g_kh);
    cudaGetSymbolAddress((void**)&kL,    g_kl);
    cudaGetSymbolAddress((void**)&v,     g_v);
    cudaGetSymbolAddress((void**)&ao,    g_ao);
    cudaGetSymbolAddress((void**)&q,     g_q);

    cudaFuncSetAttribute(gemm3_kernel,
                         cudaFuncAttributeMaxDynamicSharedMemorySize, G3_SMEM);
    cudaFuncSetAttribute(gemm2_kernel,
                         cudaFuncAttributeMaxDynamicSharedMemorySize, G2_SMEM);
    cudaFuncSetAttribute(attn_tc_kernel,
                         cudaFuncAttributeMaxDynamicSharedMemorySize, ATT_SMEM);

    // 1) LN(x) -> split fp16
    ln_split_kernel<<<BSZ * N1, 256>>>(x, ln1_w, ln1_b, xnh, xnl);
    // 2) Wkv^T split
    transpose_split_kernel<<<dim3(2 * INNER / 32, DIM / 32), dim3(32, 8)>>>(
        Wkv, wkvTh, wkvTl, DIM, 2 * INNER);
    // 3) LN(latents)
    ln_split_kernel<<<BSZ * N2, 256>>>(latents, ln2_w, ln2_b, lnh, lnl);

    // 4) K-GEMM (3-term, split fp16 out) — profiled slot
    gemm3_kernel<<<dim3(INNER / 128, (BSZ * N1) / 128), 256, G3_SMEM>>>(
        xnh, xnl, wkvTh, wkvTl, nullptr, kH, kL, BSZ * N1, INNER, DIM, 1);

    // 5) V-GEMM (2-term, single fp16 out)
    gemm2_kernel<<<dim3(INNER / 128, (BSZ * N1) / 128), 256, G2_SMEM>>>(
        xnh, wkvTh + (size_t)INNER * DIM, wkvTl + (size_t)INNER * DIM,
        nullptr, v, BSZ * N1, INNER, DIM, 1);

    // 6-7) remaining weight transposes
    transpose_split_kernel<<<dim3(INNER / 32, DIM / 32), dim3(32, 8)>>>(
        Wq, wqTh, wqTl, DIM, INNER);
    transpose_split_kernel<<<dim3(DIM / 32, INNER / 32), dim3(32, 8)>>>(
        Wout, woTh, woTl, INNER, DIM);

    // 8) q-GEMM (3-term, fp32 out)
    gemm3_kernel<<<dim3(INNER / 128, (BSZ * N2) / 128), 256, G3_SMEM>>>(
        lnh, lnl, wqTh, wqTl, q, nullptr, nullptr, BSZ * N2, INNER, DIM, 0);

    // 9) attention (S 3-term, PV 1-term)
    attn_tc_kernel<<<dim3(BSZ * HEADS, N2 / 64), 256, ATT_SMEM>>>(
        q, kH, kL, v, shift, scale, ao);

    // 10) out-GEMM (2-term, fp32 out)
    gemm2_kernel<<<dim3(DIM / 128, (BSZ * N2) / 128), 256, G2_SMEM>>>(
        ao, woTh, woTl, out, nullptr, BSZ * N2, DIM, INNER, 0);
}

// round 15
// speedup vs baseline: 1.2077x; 1.1008x over previous
#include <cuda_runtime.h>
#include <cuda_fp16.h>
#include <cstdint>
#include <math.h>

// Problem constants
#define BSZ   4
#define N1    4096
#define N2    256
#define DIM   1024
#define HEADS 16
#define DH    64
#define INNER 1024
#define EPS   1e-5f

// ---------------------------------------------------------------------------
// Scratch (device globals). fp16 (hi, lo) pairs where the softmax path needs
// near-fp32 precision; single fp16 on the unamplified V/P/ao path.
// ---------------------------------------------------------------------------
__device__ __half g_xnh[BSZ * N1 * DIM];
__device__ __half g_xnl[BSZ * N1 * DIM];
__device__ __half g_lnh[BSZ * N2 * DIM];
__device__ __half g_lnl[BSZ * N2 * DIM];
__device__ __half g_wqTh[INNER * DIM];
__device__ __half g_wqTl[INNER * DIM];
__device__ __half g_wkvTh[2 * INNER * DIM];
__device__ __half g_wkvTl[2 * INNER * DIM];
__device__ __half g_woTh[DIM * INNER];
__device__ __half g_woTl[DIM * INNER];
__device__ __half g_kh[BSZ * N1 * INNER];
__device__ __half g_kl[BSZ * N1 * INNER];
__device__ __half g_v [BSZ * N1 * INNER];
__device__ __half g_ao[BSZ * N2 * INNER];
__device__ float  g_q [BSZ * N2 * INNER];

// ---------------------------------------------------------------------------
// Helpers
// ---------------------------------------------------------------------------
__device__ __forceinline__ void mma_f16(float* c, const uint32_t* a, const uint32_t* b) {
    asm volatile(
        "mma.sync.aligned.m16n8k16.row.col.f32.f16.f16.f32 "
        "{%0,%1,%2,%3}, {%4,%5,%6,%7}, {%8,%9}, {%0,%1,%2,%3};"
        : "+f"(c[0]), "+f"(c[1]), "+f"(c[2]), "+f"(c[3])
        : "r"(a[0]), "r"(a[1]), "r"(a[2]), "r"(a[3]), "r"(b[0]), "r"(b[1]));
}

__device__ __forceinline__ void ldsm4(uint32_t* r, uint32_t addr) {
    asm volatile("ldmatrix.sync.aligned.m8n8.x4.shared.b16 {%0,%1,%2,%3}, [%4];"
                 : "=r"(r[0]), "=r"(r[1]), "=r"(r[2]), "=r"(r[3]) : "r"(addr));
}

__device__ __forceinline__ void ldsm2(uint32_t* r, uint32_t addr) {
    asm volatile("ldmatrix.sync.aligned.m8n8.x2.shared.b16 {%0,%1}, [%2];"
                 : "=r"(r[0]), "=r"(r[1]) : "r"(addr));
}

__device__ __forceinline__ void ldsm2t(uint32_t* r, uint32_t addr) {
    asm volatile("ldmatrix.sync.aligned.m8n8.x2.trans.shared.b16 {%0,%1}, [%2];"
                 : "=r"(r[0]), "=r"(r[1]) : "r"(addr));
}

__device__ __forceinline__ uint32_t pack_f16(float x, float y) {
    __half2 h = __floats2half2_rn(x, y);
    return *reinterpret_cast<uint32_t*>(&h);
}

__device__ __forceinline__ uint32_t smem_u32p(const void* p) {
    uint32_t a;
    asm("{ .reg .u64 t; cvta.to.shared.u64 t, %1; cvt.u32.u64 %0, t; }" : "=r"(a) : "l"(p));
    return a;
}

__device__ __forceinline__ void cp16(uint32_t dst, const void* src) {
    asm volatile("cp.async.cg.shared.global [%0], [%1], 16;" :: "r"(dst), "l"(src));
}

__device__ __forceinline__ float block_sum_256(float v, float* sbuf) {
    #pragma unroll
    for (int off = 16; off > 0; off >>= 1)
        v += __shfl_xor_sync(0xffffffffu, v, off);
    int w = threadIdx.x >> 5;
    if ((threadIdx.x & 31) == 0) sbuf[w] = v;
    __syncthreads();
    float r = (threadIdx.x < 8) ? sbuf[threadIdx.x] : 0.0f;
    #pragma unroll
    for (int off = 4; off > 0; off >>= 1)
        r += __shfl_xor_sync(0xffffffffu, r, off);
    if (threadIdx.x == 0) sbuf[0] = r;
    __syncthreads();
    float out = sbuf[0];
    __syncthreads();
    return out;
}

// ---------------------------------------------------------------------------
// LayerNorm (row of 1024) -> split fp16 hi/lo outputs.
// ---------------------------------------------------------------------------
__global__ void ln_split_kernel(const float* __restrict__ x,
                                const float* __restrict__ w,
                                const float* __restrict__ b,
                                __half* __restrict__ yh,
                                __half* __restrict__ yl) {
    __shared__ float sbuf[8];
    size_t row = blockIdx.x;
    int t = threadIdx.x;

    const float4 v = ((const float4*)(x + row * DIM))[t];
    float s = v.x + v.y + v.z + v.w;
    float tot = block_sum_256(s, sbuf);
    float mean = tot * (1.0f / DIM);

    float dx = v.x - mean, dy = v.y - mean, dz = v.z - mean, dw = v.w - mean;
    float sq = dx * dx + dy * dy + dz * dz + dw * dw;
    float vtot = block_sum_256(sq, sbuf);
    float inv = rsqrtf(vtot * (1.0f / DIM) + EPS);

    const float4 wv = ((const float4*)w)[t];
    const float4 bv = ((const float4*)b)[t];
    float o0 = dx * inv * wv.x + bv.x;
    float o1 = dy * inv * wv.y + bv.y;
    float o2 = dz * inv * wv.z + bv.z;
    float o3 = dw * inv * wv.w + bv.w;

    float h0 = __half2float(__float2half_rn(o0));
    float h1 = __half2float(__float2half_rn(o1));
    float h2 = __half2float(__float2half_rn(o2));
    float h3 = __half2float(__float2half_rn(o3));

    ((uint2*)(yh + row * DIM))[t] = make_uint2(pack_f16(h0, h1), pack_f16(h2, h3));
    ((uint2*)(yl + row * DIM))[t] = make_uint2(pack_f16(o0 - h0, o1 - h1),
                                               pack_f16(o2 - h2, o3 - h3));
}

// ---------------------------------------------------------------------------
// 32x32 tiled transpose with fp16 hi/lo split
// ---------------------------------------------------------------------------
__global__ void transpose_split_kernel(const float* __restrict__ in,
                                       __half* __restrict__ outh,
                                       __half* __restrict__ outl,
                                       int R, int C) {
    __shared__ float t[32][33];
    int c0 = blockIdx.x * 32, r0 = blockIdx.y * 32;
    #pragma unroll
    for (int i = 0; i < 32; i += 8)
        t[threadIdx.y + i][threadIdx.x] =
            in[(size_t)(r0 + threadIdx.y + i) * C + c0 + threadIdx.x];
    __syncthreads();
    #pragma unroll
    for (int i = 0; i < 32; i += 8) {
        float v = t[threadIdx.x][threadIdx.y + i];
        __half h = __float2half_rn(v);
        size_t idx = (size_t)(c0 + threadIdx.y + i) * R + r0 + threadIdx.x;
        outh[idx] = h;
        outl[idx] = __float2half_rn(v - __half2float(h));
    }
}

// ---------------------------------------------------------------------------
// 3-term fp16 GEMM (both operands split pairs):
//   C = Ah·Bh^T + Ah·Bl^T + Al·Bh^T
// 2-stage cp.async double buffer, 2 CTAs/SM, ldmatrix fragment loads,
// term-outer MMA ordering (dependency distance 4 on accumulators).
// ---------------------------------------------------------------------------
#define RS 20
#define MATW (128 * RS)
#define ST3_W (4 * MATW)
#define G3_SMEM (2 * ST3_W * 4)         // 81920 B

__global__ void __launch_bounds__(256, 2)
gemm3_kernel(const __half* __restrict__ Ah, const __half* __restrict__ Al,
             const __half* __restrict__ Bh, const __half* __restrict__ Bl,
             float* __restrict__ C, __half* __restrict__ Ch, __half* __restrict__ Cl,
             int M, int N, int K, int split_out) {
    extern __shared__ uint32_t sh[];
    const uint32_t sbase = smem_u32p(sh);

    const int tid  = threadIdx.x;
    const int lane = tid & 31;
    const int wid  = tid >> 5;
    const int warp_m = wid >> 2;
    const int warp_n = wid & 3;
    const int bm = blockIdx.y * 128;
    const int bn = blockIdx.x * 128;

    const int matB = tid >> 7;
    const int lt   = tid & 127;
    const int lf   = lt & 3;
    const int lr0  = lt >> 2;
    const __half* srcH = matB ? (Bh + (size_t)bn * K) : (Ah + (size_t)bm * K);
    const __half* srcL = matB ? (Bl + (size_t)bn * K) : (Al + (size_t)bm * K);
    const uint32_t dH_bytes = (matB ? 2 * MATW : 0) * 4;
    const uint32_t dL_bytes = dH_bytes + MATW * 4;

    const uint32_t arow_off =
        ((uint32_t)(warp_m * 64 + (lane & 7) + ((lane >> 3) & 1) * 8) * RS
         + (uint32_t)(lane >> 4) * 4) * 4;
    const uint32_t brow_off =
        ((uint32_t)(warp_n * 32 + (lane & 7)) * RS
         + (uint32_t)((lane >> 3) & 1) * 4) * 4;

    float acc[4][4][4];
    #pragma unroll
    for (int i = 0; i < 4; i++)
        #pragma unroll
        for (int j = 0; j < 4; j++)
            #pragma unroll
            for (int k = 0; k < 4; k++) acc[i][j][k] = 0.0f;

    const int S = K >> 5;

    #pragma unroll
    for (int pre = 0; pre < 2; pre++) {
        uint32_t stbase = sbase + (uint32_t)(pre * ST3_W * 4);
        #pragma unroll
        for (int i = 0; i < 4; i++) {
            int row = lr0 + 32 * i;
            uint32_t doff = (uint32_t)((row * RS + lf * 4) * 4);
            cp16(stbase + dH_bytes + doff, srcH + (size_t)row * K + pre * 32 + lf * 8);
            cp16(stbase + dL_bytes + doff, srcL + (size_t)row * K + pre * 32 + lf * 8);
        }
        asm volatile("cp.async.commit_group;" ::: "memory");
    }

    for (int s = 0; s < S; s++) {
        asm volatile("cp.async.wait_group 1;" ::: "memory");
        __syncthreads();

        const uint32_t stb = sbase + (uint32_t)((s & 1) * ST3_W * 4);
        const uint32_t aAH = stb + arow_off;
        const uint32_t bBH = stb + 2 * MATW * 4 + brow_off;

        #pragma unroll
        for (int ks = 0; ks < 2; ks++) {
            uint32_t bh[4][2], bl[4][2];
            #pragma unroll
            for (int nb = 0; nb < 4; nb++) {
                uint32_t ba = bBH + nb * (8 * RS * 4) + ks * 32;
                ldsm2(bh[nb], ba);
                ldsm2(bl[nb], ba + MATW * 4);
            }
            #pragma unroll
            for (int ma = 0; ma < 4; ma++) {
                uint32_t aa = aAH + ma * (16 * RS * 4) + ks * 32;
                uint32_t ah[4], al[4];
                ldsm4(ah, aa);
                ldsm4(al, aa + MATW * 4);
                // term-outer, nb-inner: consecutive MMAs hit different accs
                #pragma unroll
                for (int nb = 0; nb < 4; nb++) mma_f16(acc[ma][nb], ah, bh[nb]);
                #pragma unroll
                for (int nb = 0; nb < 4; nb++) mma_f16(acc[ma][nb], ah, bl[nb]);
                #pragma unroll
                for (int nb = 0; nb < 4; nb++) mma_f16(acc[ma][nb], al, bh[nb]);
            }
        }
        __syncthreads();

        if (s + 2 < S) {
            int k0 = (s + 2) * 32;
            uint32_t stbase = sbase + (uint32_t)((s & 1) * ST3_W * 4);
            #pragma unroll
            for (int i = 0; i < 4; i++) {
                int row = lr0 + 32 * i;
                uint32_t doff = (uint32_t)((row * RS + lf * 4) * 4);
                cp16(stbase + dH_bytes + doff, srcH + (size_t)row * K + k0 + lf * 8);
                cp16(stbase + dL_bytes + doff, srcL + (size_t)row * K + k0 + lf * 8);
            }
        }
        asm volatile("cp.async.commit_group;" ::: "memory");
    }

    uint32_t* Hh = (uint32_t*)Ch;
    uint32_t* Hl = (uint32_t*)Cl;
    #pragma unroll
    for (int ma = 0; ma < 4; ma++) {
        int row = bm + warp_m * 64 + ma * 16 + (lane >> 2);
        #pragma unroll
        for (int nb = 0; nb < 4; nb++) {
            int col = bn + warp_n * 32 + nb * 8 + (lane & 3) * 2;
            if (split_out) {
                float v0 = acc[ma][nb][0], v1 = acc[ma][nb][1];
                float v2 = acc[ma][nb][2], v3 = acc[ma][nb][3];
                float h0 = __half2float(__float2half_rn(v0));
                float h1 = __half2float(__float2half_rn(v1));
                float h2 = __half2float(__float2half_rn(v2));
                float h3 = __half2float(__float2half_rn(v3));
                size_t i0 = ((size_t)row * N + col) >> 1;
                size_t i1 = ((size_t)(row + 8) * N + col) >> 1;
                Hh[i0] = pack_f16(h0, h1);
                Hl[i0] = pack_f16(v0 - h0, v1 - h1);
                Hh[i1] = pack_f16(h2, h3);
                Hl[i1] = pack_f16(v2 - h2, v3 - h3);
            } else {
                *(float2*)(C + (size_t)row * N + col) =
                    make_float2(acc[ma][nb][0], acc[ma][nb][1]);
                *(float2*)(C + (size_t)(row + 8) * N + col) =
                    make_float2(acc[ma][nb][2], acc[ma][nb][3]);
            }
        }
    }
}

// ---------------------------------------------------------------------------
// 2-term fp16 GEMM (A single, B split pair): C = A·Bh^T + A·Bl^T
// ---------------------------------------------------------------------------
#define ST2_W (3 * MATW)
#define G2_SMEM (2 * ST2_W * 4)         // 61440 B

__global__ void __launch_bounds__(256, 2)
gemm2_kernel(const __half* __restrict__ A,
             const __half* __restrict__ Bh, const __half* __restrict__ Bl,
             float* __restrict__ C, __half* __restrict__ Ch,
             int M, int N, int K, int half_out) {
    extern __shared__ uint32_t sh[];
    const uint32_t sbase = smem_u32p(sh);

    const int tid  = threadIdx.x;
    const int lane = tid & 31;
    const int wid  = tid >> 5;
    const int warp_m = wid >> 2;
    const int warp_n = wid & 3;
    const int bm = blockIdx.y * 128;
    const int bn = blockIdx.x * 128;

    const int matB = tid >> 7;
    const int lt   = tid & 127;
    const int lf   = lt & 3;
    const int lr0  = lt >> 2;
    const __half* srcA  = A  + (size_t)bm * K;
    const __half* srcBh = Bh + (size_t)bn * K;
    const __half* srcBl = Bl + (size_t)bn * K;

    const uint32_t arow_off =
        ((uint32_t)(warp_m * 64 + (lane & 7) + ((lane >> 3) & 1) * 8) * RS
         + (uint32_t)(lane >> 4) * 4) * 4;
    const uint32_t brow_off =
        ((uint32_t)(warp_n * 32 + (lane & 7)) * RS
         + (uint32_t)((lane >> 3) & 1) * 4) * 4;

    float acc[4][4][4];
    #pragma unroll
    for (int i = 0; i < 4; i++)
        #pragma unroll
        for (int j = 0; j < 4; j++)
            #pragma unroll
            for (int k = 0; k < 4; k++) acc[i][j][k] = 0.0f;

    const int S = K >> 5;

    #pragma unroll
    for (int pre = 0; pre < 2; pre++) {
        uint32_t stbase = sbase + (uint32_t)(pre * ST2_W * 4);
        #pragma unroll
        for (int i = 0; i < 4; i++) {
            int row = lr0 + 32 * i;
            uint32_t doff = (uint32_t)((row * RS + lf * 4) * 4);
            if (matB == 0) {
                cp16(stbase + doff, srcA + (size_t)row * K + pre * 32 + lf * 8);
            } else {
                cp16(stbase + MATW * 4 + doff,     srcBh + (size_t)row * K + pre * 32 + lf * 8);
                cp16(stbase + 2 * MATW * 4 + doff, srcBl + (size_t)row * K + pre * 32 + lf * 8);
            }
        }
        asm volatile("cp.async.commit_group;" ::: "memory");
    }

    for (int s = 0; s < S; s++) {
        asm volatile("cp.async.wait_group 1;" ::: "memory");
        __syncthreads();

        const uint32_t stb = sbase + (uint32_t)((s & 1) * ST2_W * 4);
        const uint32_t aA  = stb + arow_off;
        const uint32_t bBH = stb + MATW * 4 + brow_off;

        #pragma unroll
        for (int ks = 0; ks < 2; ks++) {
            uint32_t bh[4][2], bl[4][2];
            #pragma unroll
            for (int nb = 0; nb < 4; nb++) {
                uint32_t ba = bBH + nb * (8 * RS * 4) + ks * 32;
                ldsm2(bh[nb], ba);
                ldsm2(bl[nb], ba + MATW * 4);
            }
            #pragma unroll
            for (int ma = 0; ma < 4; ma++) {
                uint32_t a[4];
                ldsm4(a, aA + ma * (16 * RS * 4) + ks * 32);
                #pragma unroll
                for (int nb = 0; nb < 4; nb++) mma_f16(acc[ma][nb], a, bh[nb]);
                #pragma unroll
                for (int nb = 0; nb < 4; nb++) mma_f16(acc[ma][nb], a, bl[nb]);
            }
        }
        __syncthreads();

        if (s + 2 < S) {
            int k0 = (s + 2) * 32;
            uint32_t stbase = sbase + (uint32_t)((s & 1) * ST2_W * 4);
            #pragma unroll
            for (int i = 0; i < 4; i++) {
                int row = lr0 + 32 * i;
                uint32_t doff = (uint32_t)((row * RS + lf * 4) * 4);
                if (matB == 0) {
                    cp16(stbase + doff, srcA + (size_t)row * K + k0 + lf * 8);
                } else {
                    cp16(stbase + MATW * 4 + doff,     srcBh + (size_t)row * K + k0 + lf * 8);
                    cp16(stbase + 2 * MATW * 4 + doff, srcBl + (size_t)row * K + k0 + lf * 8);
                }
            }
        }
        asm volatile("cp.async.commit_group;" ::: "memory");
    }

    uint32_t* H = (uint32_t*)Ch;
    #pragma unroll
    for (int ma = 0; ma < 4; ma++) {
        int row = bm + warp_m * 64 + ma * 16 + (lane >> 2);
        #pragma unroll
        for (int nb = 0; nb < 4; nb++) {
            int col = bn + warp_n * 32 + nb * 8 + (lane & 3) * 2;
            if (half_out) {
                H[((size_t)row * N + col) >> 1] =
                    pack_f16(acc[ma][nb][0], acc[ma][nb][1]);
                H[((size_t)(row + 8) * N + col) >> 1] =
                    pack_f16(acc[ma][nb][2], acc[ma][nb][3]);
            } else {
                *(float2*)(C + (size_t)row * N + col) =
                    make_float2(acc[ma][nb][0], acc[ma][nb][1]);
                *(float2*)(C + (size_t)(row + 8) * N + col) =
                    make_float2(acc[ma][nb][2], acc[ma][nb][3]);
            }
        }
    }
}

// ---------------------------------------------------------------------------
// Tensor-core flash attention per (b, h, 64-query tile).
// K and V stored row-major [key][d] via direct 16B copies (no scatter).
// S B-frags: ldsm2 (gemm pattern). PV B-frags: ldsm2.trans on V.
// P reload: ldsm4 (gemm A pattern). Term-outer S-MMA ordering.
// ---------------------------------------------------------------------------
#define AST 36
#define AMAT (64 * AST)
#define A_KH 0
#define A_KL (AMAT)
#define A_VH (2 * AMAT)
#define A_PH (3 * AMAT)
#define A_RED (4 * AMAT)
#define ATT_SMEM ((4 * AMAT + 256) * 4)

__global__ void __launch_bounds__(256, 2)
attn_tc_kernel(const float* __restrict__ q,
               const __half* __restrict__ kh,
               const __half* __restrict__ kl,
               const __half* __restrict__ vv,
               const float* __restrict__ shift,
               const float* __restrict__ scale,
               __half* __restrict__ outp) {
    extern __shared__ uint32_t ash[];
    const uint32_t abase = smem_u32p(ash);
    float* redmax = (float*)(ash + A_RED);
    float* redsum = redmax + 128;

    const int bh = blockIdx.x;
    const int b  = bh >> 4;
    const int h  = bh & 15;
    const int qt = blockIdx.y;

    const int tid  = threadIdx.x;
    const int lane = tid & 31;
    const int wid  = tid >> 5;
    const int wm   = wid >> 1;
    const int wx   = wid & 1;
    const int r    = lane >> 2;
    const int c    = lane & 3;

    const float sc = 1.0f + scale[b * HEADS + h];
    const float sh = shift[b * HEADS + h];
    const float qmul = 0.125f;

    // ldmatrix base offsets (bytes)
    const uint32_t kfrag = abase +
        (uint32_t)((A_KH + (wx * 32 + (lane & 7)) * AST + ((lane >> 3) & 1) * 4) * 4);
    const uint32_t vfrag = abase +
        (uint32_t)((A_VH + (lane & 15) * AST + wx * 16) * 4);
    const uint32_t pfrag = abase +
        (uint32_t)((A_PH + (wm * 16 + (lane & 7) + ((lane >> 3) & 1) * 8) * AST
                    + (lane >> 4) * 4) * 4);

    uint32_t qhf[4][4], qlf[4][4];
    {
        int rowA = qt * 64 + wm * 16 + r;
        const float* qA = q + ((size_t)(b * N2 + rowA)) * INNER + h * DH;
        const float* qB = qA + (size_t)8 * INNER;
        #pragma unroll
        for (int ks = 0; ks < 4; ks++) {
            int d0 = ks * 16 + c * 2;
            #pragma unroll
            for (int half = 0; half < 2; half++) {
                float2 vA = *(const float2*)(qA + d0 + half * 8);
                float2 vB = *(const float2*)(qB + d0 + half * 8);
                float ax = (vA.x * sc + sh) * qmul, ay = (vA.y * sc + sh) * qmul;
                float bx = (vB.x * sc + sh) * qmul, by = (vB.y * sc + sh) * qmul;
                float hax = __half2float(__float2half_rn(ax));
                float hay = __half2float(__float2half_rn(ay));
                float hbx = __half2float(__float2half_rn(bx));
                float hby = __half2float(__float2half_rn(by));
                qhf[ks][half * 2 + 0] = pack_f16(hax, hay);
                qhf[ks][half * 2 + 1] = pack_f16(hbx, hby);
                qlf[ks][half * 2 + 0] = pack_f16(ax - hax, ay - hay);
                qlf[ks][half * 2 + 1] = pack_f16(bx - hbx, by - hby);
            }
        }
    }

    float o[4][4];
    #pragma unroll
    for (int i = 0; i < 4; i++)
        #pragma unroll
        for (int j = 0; j < 4; j++) o[i][j] = 0.0f;
    float mA = -INFINITY, mB = -INFINITY, lA = 0.0f, lB = 0.0f;

    for (int kt = 0; kt < N1 / 64; kt++) {
        __syncthreads();

        // ---- load K hi/lo + V tiles: direct 16B copies, row-major [key][d] ----
        #pragma unroll
        for (int i = 0; i < 2; i++) {
            int idx = tid + 256 * i;
            int key = idx >> 3;
            int c8  = idx & 7;
            size_t gbase = ((size_t)(b * N1 + kt * 64 + key)) * INNER + h * DH + c8 * 8;
            *(uint4*)(ash + A_KH + key * AST + c8 * 4) = *(const uint4*)(kh + gbase);
            *(uint4*)(ash + A_KL + key * AST + c8 * 4) = *(const uint4*)(kl + gbase);
            *(uint4*)(ash + A_VH + key * AST + c8 * 4) = *(const uint4*)(vv + gbase);
        }
        __syncthreads();

        // ---- S = Qmod @ K^T : 3-term fp16, ldmatrix B-frags ----
        float s[4][4];
        #pragma unroll
        for (int i = 0; i < 4; i++)
            #pragma unroll
            for (int j = 0; j < 4; j++) s[i][j] = 0.0f;

        #pragma unroll
        for (int ks = 0; ks < 4; ks++) {
            uint32_t bh2[4][2], bl2[4][2];
            #pragma unroll
            for (int atom = 0; atom < 4; atom++) {
                uint32_t ba = kfrag + atom * (8 * AST * 4) + ks * 32;
                ldsm2(bh2[atom], ba);
                ldsm2(bl2[atom], ba + AMAT * 4);
            }
            #pragma unroll
            for (int atom = 0; atom < 4; atom++) mma_f16(s[atom], qhf[ks], bh2[atom]);
            #pragma unroll
            for (int atom = 0; atom < 4; atom++) mma_f16(s[atom], qhf[ks], bl2[atom]);
            #pragma unroll
            for (int atom = 0; atom < 4; atom++) mma_f16(s[atom], qlf[ks], bh2[atom]);
        }

        // ---- online softmax ----
        float mxA = s[0][0], mxB = s[0][2];
        #pragma unroll
        for (int atom = 0; atom < 4; atom++) {
            mxA = fmaxf(mxA, fmaxf(s[atom][0], s[atom][1]));
            mxB = fmaxf(mxB, fmaxf(s[atom][2], s[atom][3]));
        }
        mxA = fmaxf(mxA, __shfl_xor_sync(0xffffffffu, mxA, 1));
        mxA = fmaxf(mxA, __shfl_xor_sync(0xffffffffu, mxA, 2));
        mxB = fmaxf(mxB, __shfl_xor_sync(0xffffffffu, mxB, 1));
        mxB = fmaxf(mxB, __shfl_xor_sync(0xffffffffu, mxB, 2));
        if (c == 0) {
            redmax[(wm * 16 + r) * 2 + wx] = mxA;
            redmax[(wm * 16 + r + 8) * 2 + wx] = mxB;
        }
        __syncthreads();

        float mnA = fmaxf(mA, fmaxf(redmax[(wm * 16 + r) * 2],
                                    redmax[(wm * 16 + r) * 2 + 1]));
        float mnB = fmaxf(mB, fmaxf(redmax[(wm * 16 + r + 8) * 2],
                                    redmax[(wm * 16 + r + 8) * 2 + 1]));
        float alphaA = __expf(mA - mnA);
        float alphaB = __expf(mB - mnB);
        mA = mnA; mB = mnB;

        float sumA = 0.0f, sumB = 0.0f;
        #pragma unroll
        for (int atom = 0; atom < 4; atom++) {
            s[atom][0] = __expf(s[atom][0] - mnA);
            s[atom][1] = __expf(s[atom][1] - mnA);
            s[atom][2] = __expf(s[atom][2] - mnB);
            s[atom][3] = __expf(s[atom][3] - mnB);
            sumA += s[atom][0] + s[atom][1];
            sumB += s[atom][2] + s[atom][3];
        }
        sumA += __shfl_xor_sync(0xffffffffu, sumA, 1);
        sumA += __shfl_xor_sync(0xffffffffu, sumA, 2);
        sumB += __shfl_xor_sync(0xffffffffu, sumB, 1);
        sumB += __shfl_xor_sync(0xffffffffu, sumB, 2);
        if (c == 0) {
            redsum[(wm * 16 + r) * 2 + wx] = sumA;
            redsum[(wm * 16 + r + 8) * 2 + wx] = sumB;
        }

        // pack P (single fp16) -> smem, rescale O
        #pragma unroll
        for (int atom = 0; atom < 4; atom++) {
            int wpos = wx * 16 + atom * 4 + c;
            ash[A_PH + (wm * 16 + r) * AST + wpos]     = pack_f16(s[atom][0], s[atom][1]);
            ash[A_PH + (wm * 16 + r + 8) * AST + wpos] = pack_f16(s[atom][2], s[atom][3]);
            o[atom][0] *= alphaA; o[atom][1] *= alphaA;
            o[atom][2] *= alphaB; o[atom][3] *= alphaB;
        }
        __syncthreads();

        lA = lA * alphaA + redsum[(wm * 16 + r) * 2] + redsum[(wm * 16 + r) * 2 + 1];
        lB = lB * alphaB + redsum[(wm * 16 + r + 8) * 2] + redsum[(wm * 16 + r + 8) * 2 + 1];

        // ---- O += P @ V : ldsm4 P A-frags + ldsm2.trans V B-frags ----
        #pragma unroll
        for (int ks = 0; ks < 4; ks++) {
            uint32_t a2[4];
            ldsm4(a2, pfrag + ks * 32);
            #pragma unroll
            for (int atom = 0; atom < 4; atom++) {
                uint32_t b2[2];
                ldsm2t(b2, vfrag + ks * (16 * AST * 4) + atom * 16);
                mma_f16(o[atom], a2, b2);
            }
        }
    }

    float invA = 1.0f / lA, invB = 1.0f / lB;
    int rowA = qt * 64 + wm * 16 + r;
    uint32_t* o32 = (uint32_t*)outp;
    #pragma unroll
    for (int atom = 0; atom < 4; atom++) {
        int col = h * DH + wx * 32 + atom * 8 + c * 2;
        size_t iA = (((size_t)(b * N2 + rowA)) * INNER + col) >> 1;
        size_t iB = (((size_t)(b * N2 + rowA + 8)) * INNER + col) >> 1;
        o32[iA] = pack_f16(o[atom][0] * invA, o[atom][1] * invA);
        o32[iB] = pack_f16(o[atom][2] * invB, o[atom][3] * invB);
    }
}

// ---------------------------------------------------------------------------
// Launcher. K-GEMM stays in ncu slot 4.
// ---------------------------------------------------------------------------
extern "C" void kernel_launch(void* const* d_in, const int* in_sizes, int n_in,
                              void* d_out, int out_size) {
    const float* x       = (const float*)d_in[0];
    const float* latents = (const float*)d_in[1];
    const float* shift   = (const float*)d_in[2];
    const float* scale   = (const float*)d_in[3];
    const float* ln1_w   = (const float*)d_in[4];
    const float* ln1_b   = (const float*)d_in[5];
    const float* ln2_w   = (const float*)d_in[6];
    const float* ln2_b   = (const float*)d_in[7];
    const float* Wq      = (const float*)d_in[8];
    const float* Wkv     = (const float*)d_in[9];
    const float* Wout    = (const float*)d_in[10];
    float* out           = (float*)d_out;

    __half *xnh, *xnl, *lnh, *lnl, *wqTh, *wqTl, *wkvTh, *wkvTl, *woTh, *woTl;
    __half *kH, *kL, *v, *ao;
    float *q;
    cudaGetSymbolAddress((void**)&xnh,   g_xnh);
    cudaGetSymbolAddress((void**)&xnl,   g_xnl);
    cudaGetSymbolAddress((void**)&lnh,   g_lnh);
    cudaGetSymbolAddress((void**)&lnl,   g_lnl);
    cudaGetSymbolAddress((void**)&wqTh,  g_wqTh);
    cudaGetSymbolAddress((void**)&wqTl,  g_wqTl);
    cudaGetSymbolAddress((void**)&wkvTh, g_wkvTh);
    cudaGetSymbolAddress((void**)&wkvTl, g_wkvTl);
    cudaGetSymbolAddress((void**)&woTh,  g_woTh);
    cudaGetSymbolAddress((void**)&woTl,  g_woTl);
    cudaGetSymbolAddress((void**)&kH,    g_kh);
    cudaGetSymbolAddress((void**)&kL,    g_kl);
    cudaGetSymbolAddress((void**)&v,     g_v);
    cudaGetSymbolAddress((void**)&ao,    g_ao);
    cudaGetSymbolAddress((void**)&q,     g_q);

    cudaFuncSetAttribute(gemm3_kernel,
                         cudaFuncAttributeMaxDynamicSharedMemorySize, G3_SMEM);
    cudaFuncSetAttribute(gemm2_kernel,
                         cudaFuncAttributeMaxDynamicSharedMemorySize, G2_SMEM);
    cudaFuncSetAttribute(attn_tc_kernel,
                         cudaFuncAttributeMaxDynamicSharedMemorySize, ATT_SMEM);

    // 1) LN(x) -> split fp16
    ln_split_kernel<<<BSZ * N1, 256>>>(x, ln1_w, ln1_b, xnh, xnl);
    // 2) Wkv^T split
    transpose_split_kernel<<<dim3(2 * INNER / 32, DIM / 32), dim3(32, 8)>>>(
        Wkv, wkvTh, wkvTl, DIM, 2 * INNER);
    // 3) LN(latents)
    ln_split_kernel<<<BSZ * N2, 256>>>(latents, ln2_w, ln2_b, lnh, lnl);

    // 4) K-GEMM (3-term, split fp16 out) — profiled slot
    gemm3_kernel<<<dim3(INNER / 128, (BSZ * N1) / 128), 256, G3_SMEM>>>(
        xnh, xnl, wkvTh, wkvTl, nullptr, kH, kL, BSZ * N1, INNER, DIM, 1);

    // 5) V-GEMM (2-term, single fp16 out)
    gemm2_kernel<<<dim3(INNER / 128, (BSZ * N1) / 128), 256, G2_SMEM>>>(
        xnh, wkvTh + (size_t)INNER * DIM, wkvTl + (size_t)INNER * DIM,
        nullptr, v, BSZ * N1, INNER, DIM, 1);

    // 6-7) remaining weight transposes
    transpose_split_kernel<<<dim3(INNER / 32, DIM / 32), dim3(32, 8)>>>(
        Wq, wqTh, wqTl, DIM, INNER);
    transpose_split_kernel<<<dim3(DIM / 32, INNER / 32), dim3(32, 8)>>>(
        Wout, woTh, woTl, INNER, DIM);

    // 8) q-GEMM (3-term, fp32 out)
    gemm3_kernel<<<dim3(INNER / 128, (BSZ * N2) / 128), 256, G3_SMEM>>>(
        lnh, lnl, wqTh, wqTl, q, nullptr, nullptr, BSZ * N2, INNER, DIM, 0);

    // 9) attention (S 3-term, PV 1-term)
    attn_tc_kernel<<<dim3(BSZ * HEADS, N2 / 64), 256, ATT_SMEM>>>(
        q, kH, kL, v, shift, scale, ao);

    // 10) out-GEMM (2-term, fp32 out)
    gemm2_kernel<<<dim3(DIM / 128, (BSZ * N2) / 128), 256, G2_SMEM>>>(
        ao, woTh, woTl, out, nullptr, BSZ * N2, DIM, INNER, 0);
}